// round 4
// baseline (speedup 1.0000x reference)
#include <cuda_runtime.h>
#include <cstdint>

#define NUM_B 16
#define SEQ_N 1025
#define NHEAD 12
#define HDIM  64
#define DMODEL 768
#define M_ROWS (NUM_B * SEQ_N)   // 16400

// ---------------- scratch ----------------
__device__ float g_Q[NUM_B * NHEAD * SEQ_N * HDIM];
__device__ float g_K[NUM_B * NHEAD * SEQ_N * HDIM];
__device__ float g_V[NUM_B * NHEAD * SEQ_N * HDIM];
__device__ float g_ctx[NUM_B * SEQ_N * DMODEL];

__device__ __forceinline__ uint32_t f2tf(float f) {
    uint32_t r;
    asm("cvt.rna.tf32.f32 %0, %1;" : "=r"(r) : "f"(f));
    return r;
}
__device__ __forceinline__ void mma8(float* c, const uint32_t* a, const uint32_t* b) {
    asm volatile(
        "mma.sync.aligned.m16n8k8.row.col.f32.tf32.tf32.f32 "
        "{%0,%1,%2,%3}, {%4,%5,%6,%7}, {%8,%9}, {%0,%1,%2,%3};\n"
        : "+f"(c[0]), "+f"(c[1]), "+f"(c[2]), "+f"(c[3])
        : "r"(a[0]), "r"(a[1]), "r"(a[2]), "r"(a[3]), "r"(b[0]), "r"(b[1]));
}

// =================================================================
// TN GEMM, tf32 TC. Block 128x64, 256 threads, 8 warps (4m x 2n),
// warp tile 32x32, k-step 32, 2-stage double buffer, packed frags.
// MODE 0: RoPE epilogue -> g_Q/g_K/g_V. MODE 1: +bias -> out.
// =================================================================
template<int MODE>
__global__ __launch_bounds__(256, 2) void gemm_tc(
    const float* __restrict__ A, const float* __restrict__ Bw,
    float* __restrict__ out, const float* __restrict__ bias,
    const float* __restrict__ freqs)
{
    // Apk: mb(8) x kb(4) x lane(32) x reg(4) per stage = 4096 u32
    // Bpk: nb(8) x kb(4) x lane(32) x reg(2) per stage = 2048 u32
    __shared__ uint32_t Apk[2][4096];
    __shared__ uint32_t Bpk[2][2048];

    const int tid = threadIdx.x;
    const int lane = tid & 31;
    const int wid = tid >> 5;
    const int wm = wid & 3;       // 0..3
    const int wn = wid >> 2;      // 0..1
    const int m0 = blockIdx.x * 128;
    const int n0 = blockIdx.y * 64;

    const float* Ap = (MODE == 1) ? g_ctx : A;

    float c[2][4][4];
#pragma unroll
    for (int i = 0; i < 2; i++)
#pragma unroll
        for (int j = 0; j < 4; j++)
#pragma unroll
            for (int r = 0; r < 4; r++) c[i][j][r] = 0.f;

    const int col4 = tid & 7;           // k-float4 index: k = col4*4 + j
    const int rowL = tid >> 3;          // 0..31

    float4 ar[4], br[2];

    auto loadA = [&](int k0) {
#pragma unroll
        for (int p = 0; p < 4; p++) {
            int gm = m0 + rowL + p * 32;
            ar[p] = make_float4(0.f, 0.f, 0.f, 0.f);
            if (gm < M_ROWS) ar[p] = *(const float4*)&Ap[(size_t)gm * DMODEL + k0 + col4 * 4];
        }
    };
    auto loadB = [&](int k0) {
#pragma unroll
        for (int p = 0; p < 2; p++) {
            int gn = n0 + rowL + p * 32;
            br[p] = *(const float4*)&Bw[(size_t)gn * DMODEL + k0 + col4 * 4];
        }
    };
    auto storeA = [&](int s) {
#pragma unroll
        for (int p = 0; p < 4; p++) {
            int r = rowL + p * 32;
            uint32_t* pp = &Apk[s][(((r >> 4) * 4 + (col4 >> 1)) << 7) + ((r & 7) << 4)
                                   + (((r >> 3) & 1) | ((col4 & 1) << 1))];
            pp[0]  = f2tf(ar[p].x);
            pp[4]  = f2tf(ar[p].y);
            pp[8]  = f2tf(ar[p].z);
            pp[12] = f2tf(ar[p].w);
        }
    };
    auto storeB = [&](int s) {
#pragma unroll
        for (int p = 0; p < 2; p++) {
            int r = rowL + p * 32;
            uint32_t* pp = &Bpk[s][(((r >> 3) * 4 + (col4 >> 1)) << 6) + ((r & 7) << 3)
                                   + (col4 & 1)];
            pp[0] = f2tf(br[p].x);
            pp[2] = f2tf(br[p].y);
            pp[4] = f2tf(br[p].z);
            pp[6] = f2tf(br[p].w);
        }
    };

    loadA(0); loadB(0);
    storeA(0); storeB(0);
    __syncthreads();

    int stage = 0;
    for (int k0 = 0; k0 < DMODEL; k0 += 32) {
        const bool has_next = (k0 + 32 < DMODEL);
        if (has_next) { loadA(k0 + 32); loadB(k0 + 32); }

#pragma unroll
        for (int kb = 0; kb < 4; kb++) {
            uint32_t a[2][4], b[4][2];
#pragma unroll
            for (int mt = 0; mt < 2; mt++) {
                uint4 av = *(const uint4*)&Apk[stage][(((wm * 2 + mt) * 4 + kb) << 7) + lane * 4];
                a[mt][0] = av.x; a[mt][1] = av.y; a[mt][2] = av.z; a[mt][3] = av.w;
            }
#pragma unroll
            for (int nt = 0; nt < 4; nt++) {
                uint2 bv = *(const uint2*)&Bpk[stage][(((wn * 4 + nt) * 4 + kb) << 6) + lane * 2];
                b[nt][0] = bv.x; b[nt][1] = bv.y;
            }
#pragma unroll
            for (int mt = 0; mt < 2; mt++)
#pragma unroll
                for (int nt = 0; nt < 4; nt++)
                    mma8(c[mt][nt], a[mt], b[nt]);
        }

        if (has_next) { storeA(stage ^ 1); storeB(stage ^ 1); }
        __syncthreads();
        stage ^= 1;
    }

    // -------- epilogue --------
    if (MODE == 0) {
        const int sidx = n0 / DMODEL;            // uniform per block
        const int hh = (n0 % DMODEL) >> 6;       // uniform per block (N-tile == head)
        float* dst = (sidx == 0) ? g_Q : (sidx == 1) ? g_K : g_V;
#pragma unroll
        for (int nt = 0; nt < 4; nt++) {
            int e0 = wn * 32 + nt * 8 + 2 * (lane & 3);
            float f0 = 0.f, f1 = 0.f;
            if (sidx < 2) {
                int fi = hh * 32 + (e0 >> 1);
                f0 = freqs[fi];
                f1 = freqs[384 + fi];
            }
#pragma unroll
            for (int mt = 0; mt < 2; mt++)
#pragma unroll
                for (int hr = 0; hr < 2; hr++) {
                    int row = m0 + wm * 32 + mt * 16 + (lane >> 2) + hr * 8;
                    if (row >= M_ROWS) continue;
                    int bb = row / SEQ_N;
                    int n = row - bb * SEQ_N;
                    float v0 = c[mt][nt][hr * 2 + 0];
                    float v1 = c[mt][nt][hr * 2 + 1];
                    if (sidx < 2 && n >= 1) {
                        int t = n - 1;
                        float ang = (float)(t & 31) * f0 + (float)(t >> 5) * f1;
                        float sn, cs;
                        sincosf(ang, &sn, &cs);
                        float a0 = v0, b0 = v1;
                        v0 = a0 * cs - b0 * sn;
                        v1 = a0 * sn + b0 * cs;
                    }
                    size_t off = ((size_t)((bb * NHEAD + hh) * SEQ_N + n)) * HDIM + e0;
                    *(float2*)&dst[off] = make_float2(v0, v1);
                }
        }
    } else {
#pragma unroll
        for (int nt = 0; nt < 4; nt++) {
            int col = n0 + wn * 32 + nt * 8 + 2 * (lane & 3);
            float b0v = bias[col], b1v = bias[col + 1];
#pragma unroll
            for (int mt = 0; mt < 2; mt++)
#pragma unroll
                for (int hr = 0; hr < 2; hr++) {
                    int row = m0 + wm * 32 + mt * 16 + (lane >> 2) + hr * 8;
                    if (row >= M_ROWS) continue;
                    *(float2*)&out[(size_t)row * DMODEL + col] =
                        make_float2(c[mt][nt][hr * 2 + 0] + b0v,
                                    c[mt][nt][hr * 2 + 1] + b1v);
                }
        }
    }
}

// =================================================================
// Flash attention, tf32 TC. 256 threads (8 warps), 128 q/block,
// 16 q/warp, kv tiles of 64. Q fragments live in registers;
// K/V packed shared; P via warp-private packed strip.
// smem u32: Kpk 4096 | Vpk 4096 | Ppk 8192 = 64 KB
// =================================================================
#define ATTN_SMEM_BYTES (16384 * 4)

__global__ __launch_bounds__(256, 2) void attn_tc()
{
    extern __shared__ uint32_t dsm[];
    uint32_t* Kpk = dsm;           // nb(8) x kb(8) x lane(32) x reg(2)
    uint32_t* Vpk = dsm + 4096;    // nb(8) x kb(8) x lane(32) x reg(2)
    uint32_t* Ppk = dsm + 8192;    // w(8) x kb(8) x lane(32) x reg(4)

    const int tid = threadIdx.x;
    const int lane = tid & 31;
    const int w = tid >> 5;
    const int q0 = blockIdx.x * 128;
    const int bh = blockIdx.y;
    const size_t base = (size_t)bh * SEQ_N * HDIM;
    uint32_t* Pw = Ppk + w * 1024;

    // ---- stage Q (scaled) through strip, then to registers ----
#pragma unroll
    for (int it = 0; it < 8; it++) {
        int slot = lane + it * 32;          // 256 slots = 16 rows x 16 float4
        int r = slot >> 4;
        int cg = (slot & 15) * 4;
        int gq = q0 + w * 16 + r;
        float4 v = make_float4(0.f, 0.f, 0.f, 0.f);
        if (gq < SEQ_N) v = *(const float4*)&g_Q[base + (size_t)gq * HDIM + cg];
        int reg = ((r >> 3) & 1) | (((cg >> 2) & 1) << 1);
        uint32_t* pp = &Pw[((cg >> 3) << 7) + ((r & 7) << 4) + reg];
        pp[0]  = f2tf(v.x * 0.125f);
        pp[4]  = f2tf(v.y * 0.125f);
        pp[8]  = f2tf(v.z * 0.125f);
        pp[12] = f2tf(v.w * 0.125f);
    }
    __syncwarp();
    uint32_t qa[8][4];
#pragma unroll
    for (int kb = 0; kb < 8; kb++) {
        uint4 qv = *(const uint4*)&Pw[(kb << 7) + lane * 4];
        qa[kb][0] = qv.x; qa[kb][1] = qv.y; qa[kb][2] = qv.z; qa[kb][3] = qv.w;
    }
    __syncwarp();

    float of[8][4];
#pragma unroll
    for (int i = 0; i < 8; i++)
#pragma unroll
        for (int j = 0; j < 4; j++) of[i][j] = 0.f;
    float m0r = -1e30f, m1r = -1e30f, l0 = 0.f, l1 = 0.f;

    for (int kt = 0; kt < 17; kt++) {
        const int kv0 = kt * 64;
        __syncthreads();
        // ---- stage K, V (64x64 each), packed B-frag layouts ----
#pragma unroll
        for (int it = 0; it < 4; it++) {
            int slot = tid + it * 256;       // 1024 slots = 64 rows x 16 float4
            int r = slot >> 4;               // key index in tile
            int cg = (slot & 15) * 4;        // e
            int gk = kv0 + r;
            float4 kv = make_float4(0.f, 0.f, 0.f, 0.f);
            float4 vv = make_float4(0.f, 0.f, 0.f, 0.f);
            if (gk < SEQ_N) {
                size_t off = base + (size_t)gk * HDIM + cg;
                kv = *(const float4*)&g_K[off];
                vv = *(const float4*)&g_V[off];
            }
            {   // K: n=key(r), k=e
                uint32_t* pp = &Kpk[(((r >> 3) * 8 + (cg >> 3)) << 6) + ((r & 7) << 3)
                                    + ((cg >> 2) & 1)];
                pp[0] = f2tf(kv.x);
                pp[2] = f2tf(kv.y);
                pp[4] = f2tf(kv.z);
                pp[6] = f2tf(kv.w);
            }
            {   // V: n=e, k=key(r)
                uint32_t* pp = &Vpk[(((cg >> 3) * 8 + (r >> 3)) << 6) + ((cg & 7) << 3)
                                    + ((r & 3) << 1) + ((r >> 2) & 1)];
                pp[0]  = f2tf(vv.x);
                pp[8]  = f2tf(vv.y);
                pp[16] = f2tf(vv.z);
                pp[24] = f2tf(vv.w);
            }
        }
        __syncthreads();

        // ---- S = Q K^T ----
        float s[8][4];
#pragma unroll
        for (int i = 0; i < 8; i++)
#pragma unroll
            for (int j = 0; j < 4; j++) s[i][j] = 0.f;
#pragma unroll
        for (int kb = 0; kb < 8; kb++) {
#pragma unroll
            for (int nt = 0; nt < 8; nt++) {
                uint2 bv = *(const uint2*)&Kpk[((nt * 8 + kb) << 6) + lane * 2];
                uint32_t b[2] = {bv.x, bv.y};
                mma8(s[nt], qa[kb], b);
            }
        }

        if (kt == 16) {
#pragma unroll
            for (int nt = 0; nt < 8; nt++) {
                int col = kv0 + nt * 8 + 2 * (lane & 3);
                if (col >= SEQ_N)     { s[nt][0] = -1e30f; s[nt][2] = -1e30f; }
                if (col + 1 >= SEQ_N) { s[nt][1] = -1e30f; s[nt][3] = -1e30f; }
            }
        }

        // ---- online softmax ----
        float mx0 = -1e30f, mx1 = -1e30f;
#pragma unroll
        for (int nt = 0; nt < 8; nt++) {
            mx0 = fmaxf(mx0, fmaxf(s[nt][0], s[nt][1]));
            mx1 = fmaxf(mx1, fmaxf(s[nt][2], s[nt][3]));
        }
        mx0 = fmaxf(mx0, __shfl_xor_sync(0xffffffffu, mx0, 1));
        mx0 = fmaxf(mx0, __shfl_xor_sync(0xffffffffu, mx0, 2));
        mx1 = fmaxf(mx1, __shfl_xor_sync(0xffffffffu, mx1, 1));
        mx1 = fmaxf(mx1, __shfl_xor_sync(0xffffffffu, mx1, 2));
        float mn0 = fmaxf(m0r, mx0), mn1 = fmaxf(m1r, mx1);
        float cr0 = __expf(m0r - mn0), cr1 = __expf(m1r - mn1);
        float sum0 = 0.f, sum1 = 0.f;
#pragma unroll
        for (int nt = 0; nt < 8; nt++) {
            s[nt][0] = __expf(s[nt][0] - mn0);
            s[nt][1] = __expf(s[nt][1] - mn0);
            s[nt][2] = __expf(s[nt][2] - mn1);
            s[nt][3] = __expf(s[nt][3] - mn1);
            sum0 += s[nt][0] + s[nt][1];
            sum1 += s[nt][2] + s[nt][3];
        }
        sum0 += __shfl_xor_sync(0xffffffffu, sum0, 1);
        sum0 += __shfl_xor_sync(0xffffffffu, sum0, 2);
        sum1 += __shfl_xor_sync(0xffffffffu, sum1, 1);
        sum1 += __shfl_xor_sync(0xffffffffu, sum1, 2);
        l0 = l0 * cr0 + sum0;
        l1 = l1 * cr1 + sum1;
        m0r = mn0;
        m1r = mn1;
#pragma unroll
        for (int ne = 0; ne < 8; ne++) {
            of[ne][0] *= cr0; of[ne][1] *= cr0;
            of[ne][2] *= cr1; of[ne][3] *= cr1;
        }

        // ---- P -> warp-private packed strip ----
        {
            int r0 = lane >> 2;
            int c0 = 2 * (lane & 3);
            int pb = ((r0 << 2) | (c0 & 3)) * 4 + ((c0 & 4) ? 2 : 0);
#pragma unroll
            for (int nt = 0; nt < 8; nt++) {
                uint32_t* pp = &Pw[(nt << 7) + pb];
                pp[0] = f2tf(s[nt][0]);
                pp[4] = f2tf(s[nt][1]);
                pp[1] = f2tf(s[nt][2]);
                pp[5] = f2tf(s[nt][3]);
            }
        }
        __syncwarp();

        // ---- O += P V ----
#pragma unroll
        for (int kb = 0; kb < 8; kb++) {
            uint4 pv = *(const uint4*)&Pw[(kb << 7) + lane * 4];
            uint32_t pa[4] = {pv.x, pv.y, pv.z, pv.w};
#pragma unroll
            for (int ne = 0; ne < 8; ne++) {
                uint2 bv = *(const uint2*)&Vpk[((ne * 8 + kb) << 6) + lane * 2];
                uint32_t b[2] = {bv.x, bv.y};
                mma8(of[ne], pa, b);
            }
        }
        __syncwarp();
    }

    // ---- normalize + write context ----
    float inv0 = 1.f / l0, inv1 = 1.f / l1;
    const int hh = bh % NHEAD;
    const int bb = bh / NHEAD;
    const int qr0 = q0 + w * 16 + (lane >> 2);
    const int qr1 = qr0 + 8;
#pragma unroll
    for (int ne = 0; ne < 8; ne++) {
        int e = hh * 64 + ne * 8 + 2 * (lane & 3);
        if (qr0 < SEQ_N)
            *(float2*)&g_ctx[((size_t)(bb * SEQ_N + qr0)) * DMODEL + e] =
                make_float2(of[ne][0] * inv0, of[ne][1] * inv0);
        if (qr1 < SEQ_N)
            *(float2*)&g_ctx[((size_t)(bb * SEQ_N + qr1)) * DMODEL + e] =
                make_float2(of[ne][2] * inv1, of[ne][3] * inv1);
    }
}

// =================================================================
extern "C" void kernel_launch(void* const* d_in, const int* in_sizes, int n_in,
                              void* d_out, int out_size)
{
    const float* x     = (const float*)d_in[0];
    const float* Wqkv  = (const float*)d_in[1];
    const float* Wproj = (const float*)d_in[2];
    const float* bproj = (const float*)d_in[3];
    const float* freqs = (const float*)d_in[4];
    float* out = (float*)d_out;

    {
        dim3 grid((M_ROWS + 127) / 128, (3 * DMODEL) / 64);
        gemm_tc<0><<<grid, 256>>>(x, Wqkv, nullptr, nullptr, freqs);
    }
    {
        cudaFuncSetAttribute(attn_tc,
                             cudaFuncAttributeMaxDynamicSharedMemorySize,
                             ATTN_SMEM_BYTES);
        dim3 grid((SEQ_N + 127) / 128, NUM_B * NHEAD);
        attn_tc<<<grid, 256, ATTN_SMEM_BYTES>>>();
    }
    {
        dim3 grid((M_ROWS + 127) / 128, DMODEL / 64);
        gemm_tc<1><<<grid, 256>>>(nullptr, Wproj, out, bproj, nullptr);
    }
}

// round 5
// speedup vs baseline: 1.7049x; 1.7049x over previous
#include <cuda_runtime.h>
#include <cstdint>

#define NUM_B 16
#define SEQ_N 1025
#define NHEAD 12
#define HDIM  64
#define DMODEL 768
#define M_ROWS (NUM_B * SEQ_N)   // 16400

// ---------------- scratch ----------------
__device__ float g_Q[NUM_B * NHEAD * SEQ_N * HDIM];
__device__ float g_K[NUM_B * NHEAD * SEQ_N * HDIM];
__device__ float g_V[NUM_B * NHEAD * SEQ_N * HDIM];
__device__ float g_ctx[NUM_B * SEQ_N * DMODEL];

__device__ __forceinline__ uint32_t f2tf(float f) {
    uint32_t r;
    asm("cvt.rna.tf32.f32 %0, %1;" : "=r"(r) : "f"(f));
    return r;
}
__device__ __forceinline__ void mma8(float* c, const uint32_t* a, const uint32_t* b) {
    asm volatile(
        "mma.sync.aligned.m16n8k8.row.col.f32.tf32.tf32.f32 "
        "{%0,%1,%2,%3}, {%4,%5,%6,%7}, {%8,%9}, {%0,%1,%2,%3};\n"
        : "+f"(c[0]), "+f"(c[1]), "+f"(c[2]), "+f"(c[3])
        : "r"(a[0]), "r"(a[1]), "r"(a[2]), "r"(a[3]), "r"(b[0]), "r"(b[1]));
}

// =================================================================
// TN GEMM, tf32 TC. Block 128x128, 256 threads (8 warps, 4m x 2n),
// warp tile 32x64, k-step 32. XOR-swizzled smem (stride 32):
// data chunk c of row m stored at chunk (c ^ (m&7)).
// Staging stores = conflict-free STS.128; frag loads = CF scalar LDS.
// MODE 0: RoPE epilogue -> g_Q/g_K/g_V. MODE 1: +bias -> out.
// =================================================================
template<int MODE>
__global__ __launch_bounds__(256, 2) void gemm_tc(
    const float* __restrict__ A, const float* __restrict__ Bw,
    float* __restrict__ out, const float* __restrict__ bias,
    const float* __restrict__ freqs)
{
    __shared__ uint32_t As[128 * 32];
    __shared__ uint32_t Bs[128 * 32];

    const int tid = threadIdx.x;
    const int lane = tid & 31;
    const int wid = tid >> 5;
    const int wm = wid & 3;       // 0..3: m group of 32
    const int wn = wid >> 2;      // 0..1: n group of 64
    const int m0 = blockIdx.x * 128;
    const int n0 = blockIdx.y * 128;

    const float* Ap = (MODE == 1) ? g_ctx : A;

    float c[2][8][4];
#pragma unroll
    for (int i = 0; i < 2; i++)
#pragma unroll
        for (int j = 0; j < 8; j++)
#pragma unroll
            for (int r = 0; r < 4; r++) c[i][j][r] = 0.f;

    const int rowL = tid >> 3;          // 0..31
    const int col4 = tid & 7;           // k chunk 0..7
    const int s7 = lane >> 2;           // row&7 for frag rows
    const int l3 = lane & 3;

    for (int k0 = 0; k0 < DMODEL; k0 += 32) {
        // ---- stage A (128x32), swizzled STS.128 ----
#pragma unroll
        for (int p = 0; p < 4; p++) {
            int m = rowL + p * 32;
            int gm = m0 + m;
            float4 v = make_float4(0.f, 0.f, 0.f, 0.f);
            if (gm < M_ROWS) v = *(const float4*)&Ap[(size_t)gm * DMODEL + k0 + col4 * 4];
            uint4 u;
            u.x = f2tf(v.x); u.y = f2tf(v.y); u.z = f2tf(v.z); u.w = f2tf(v.w);
            *(uint4*)&As[m * 32 + ((col4 ^ (m & 7)) << 2)] = u;
        }
        // ---- stage B (128x32) ----
#pragma unroll
        for (int p = 0; p < 4; p++) {
            int n = rowL + p * 32;
            float4 v = *(const float4*)&Bw[(size_t)(n0 + n) * DMODEL + k0 + col4 * 4];
            uint4 u;
            u.x = f2tf(v.x); u.y = f2tf(v.y); u.z = f2tf(v.z); u.w = f2tf(v.w);
            *(uint4*)&Bs[n * 32 + ((col4 ^ (n & 7)) << 2)] = u;
        }
        __syncthreads();

#pragma unroll
        for (int kb = 0; kb < 4; kb++) {
            const int pc0 = (((2 * kb)     ^ s7) << 2) + l3;
            const int pc1 = (((2 * kb + 1) ^ s7) << 2) + l3;
            uint32_t a[2][4], b[8][2];
#pragma unroll
            for (int mt = 0; mt < 2; mt++) {
                int mr = wm * 32 + mt * 16 + s7;
                a[mt][0] = As[mr * 32 + pc0];
                a[mt][1] = As[(mr + 8) * 32 + pc0];
                a[mt][2] = As[mr * 32 + pc1];
                a[mt][3] = As[(mr + 8) * 32 + pc1];
            }
#pragma unroll
            for (int nt = 0; nt < 8; nt++) {
                int nc = wn * 64 + nt * 8 + s7;
                b[nt][0] = Bs[nc * 32 + pc0];
                b[nt][1] = Bs[nc * 32 + pc1];
            }
#pragma unroll
            for (int mt = 0; mt < 2; mt++)
#pragma unroll
                for (int nt = 0; nt < 8; nt++)
                    mma8(c[mt][nt], a[mt], b[nt]);
        }
        __syncthreads();
    }

    // -------- epilogue --------
    if (MODE == 0) {
        const int sidx = n0 / DMODEL;                      // uniform per block
        const int hh = ((n0 % DMODEL) >> 6) + wn;          // uniform per warp
        float* dst = (sidx == 0) ? g_Q : (sidx == 1) ? g_K : g_V;
#pragma unroll
        for (int nt = 0; nt < 8; nt++) {
            int e0 = nt * 8 + 2 * l3;
            float f0 = 0.f, f1 = 0.f;
            if (sidx < 2) {
                int fi = hh * 32 + (e0 >> 1);
                f0 = freqs[fi];
                f1 = freqs[384 + fi];
            }
#pragma unroll
            for (int mt = 0; mt < 2; mt++)
#pragma unroll
                for (int hr = 0; hr < 2; hr++) {
                    int row = m0 + wm * 32 + mt * 16 + s7 + hr * 8;
                    if (row >= M_ROWS) continue;
                    int bb = row / SEQ_N;
                    int n = row - bb * SEQ_N;
                    float v0 = c[mt][nt][hr * 2 + 0];
                    float v1 = c[mt][nt][hr * 2 + 1];
                    if (sidx < 2 && n >= 1) {
                        int t = n - 1;
                        float ang = (float)(t & 31) * f0 + (float)(t >> 5) * f1;
                        float sn, cs;
                        sincosf(ang, &sn, &cs);
                        float a0 = v0, b0 = v1;
                        v0 = a0 * cs - b0 * sn;
                        v1 = a0 * sn + b0 * cs;
                    }
                    size_t off = ((size_t)((bb * NHEAD + hh) * SEQ_N + n)) * HDIM + e0;
                    *(float2*)&dst[off] = make_float2(v0, v1);
                }
        }
    } else {
#pragma unroll
        for (int nt = 0; nt < 8; nt++) {
            int col = n0 + wn * 64 + nt * 8 + 2 * l3;
            float b0v = bias[col], b1v = bias[col + 1];
#pragma unroll
            for (int mt = 0; mt < 2; mt++)
#pragma unroll
                for (int hr = 0; hr < 2; hr++) {
                    int row = m0 + wm * 32 + mt * 16 + s7 + hr * 8;
                    if (row >= M_ROWS) continue;
                    *(float2*)&out[(size_t)row * DMODEL + col] =
                        make_float2(c[mt][nt][hr * 2 + 0] + b0v,
                                    c[mt][nt][hr * 2 + 1] + b1v);
                }
        }
    }
}

// =================================================================
// Flash attention, tf32 TC. 256 threads (8 warps), 128 q/block,
// 16 q/warp, kv tiles of 64. R2-proven layouts, 2x wider block
// (halves K/V staging per query). Q frags in registers.
// smem u32: Ks 64x68 | Vs 64x72 | P strips 8x16x72 = 72704 B
// =================================================================
#define ATTN_SMEM_BYTES ((64 * 68 + 64 * 72 + 8 * 16 * 72) * 4)

__global__ __launch_bounds__(256, 2) void attn_tc()
{
    extern __shared__ uint32_t dsm[];
    uint32_t* Ks = dsm;                 // [key][e] stride 68
    uint32_t* Vs = Ks + 64 * 68;        // [key][e] stride 72
    uint32_t* Ps = Vs + 64 * 72;        // per-warp strips [16][72]

    const int tid = threadIdx.x;
    const int lane = tid & 31;
    const int w = tid >> 5;
    const int q0 = blockIdx.x * 128;
    const int bh = blockIdx.y;
    const size_t base = (size_t)bh * SEQ_N * HDIM;
    uint32_t* Pw = Ps + w * 16 * 72;

    // ---- stage Q (scaled) through strip, then to registers ----
#pragma unroll
    for (int it = 0; it < 8; it++) {
        int slot = lane + it * 32;          // 256 slots = 16 rows x 16 float4
        int r = slot >> 4;
        int cg = (slot & 15) * 4;
        int gq = q0 + w * 16 + r;
        float4 v = make_float4(0.f, 0.f, 0.f, 0.f);
        if (gq < SEQ_N) v = *(const float4*)&g_Q[base + (size_t)gq * HDIM + cg];
        Pw[r * 72 + cg + 0] = f2tf(v.x * 0.125f);
        Pw[r * 72 + cg + 1] = f2tf(v.y * 0.125f);
        Pw[r * 72 + cg + 2] = f2tf(v.z * 0.125f);
        Pw[r * 72 + cg + 3] = f2tf(v.w * 0.125f);
    }
    __syncwarp();
    uint32_t qa[8][4];
#pragma unroll
    for (int kb = 0; kb < 8; kb++) {
        qa[kb][0] = Pw[(lane >> 2) * 72 + kb * 8 + (lane & 3)];
        qa[kb][1] = Pw[((lane >> 2) + 8) * 72 + kb * 8 + (lane & 3)];
        qa[kb][2] = Pw[(lane >> 2) * 72 + kb * 8 + (lane & 3) + 4];
        qa[kb][3] = Pw[((lane >> 2) + 8) * 72 + kb * 8 + (lane & 3) + 4];
    }
    __syncwarp();

    float of[8][4];
#pragma unroll
    for (int i = 0; i < 8; i++)
#pragma unroll
        for (int j = 0; j < 4; j++) of[i][j] = 0.f;
    float m0r = -1e30f, m1r = -1e30f, l0 = 0.f, l1 = 0.f;

    for (int kt = 0; kt < 17; kt++) {
        const int kv0 = kt * 64;
        __syncthreads();
        // ---- stage K, V (64x64 each) ----
#pragma unroll
        for (int it = 0; it < 4; it++) {
            int slot = tid + it * 256;       // 1024 slots = 64 rows x 16 float4
            int r = slot >> 4;
            int cg = (slot & 15) * 4;
            int gk = kv0 + r;
            float4 kv = make_float4(0.f, 0.f, 0.f, 0.f);
            float4 vv = make_float4(0.f, 0.f, 0.f, 0.f);
            if (gk < SEQ_N) {
                size_t off = base + (size_t)gk * HDIM + cg;
                kv = *(const float4*)&g_K[off];
                vv = *(const float4*)&g_V[off];
            }
            uint4 uk, uv;
            uk.x = f2tf(kv.x); uk.y = f2tf(kv.y); uk.z = f2tf(kv.z); uk.w = f2tf(kv.w);
            uv.x = f2tf(vv.x); uv.y = f2tf(vv.y); uv.z = f2tf(vv.z); uv.w = f2tf(vv.w);
            *(uint4*)&Ks[r * 68 + cg] = uk;
            *(uint4*)&Vs[r * 72 + cg] = uv;
        }
        __syncthreads();

        // ---- S = Q K^T ----
        float s[8][4];
#pragma unroll
        for (int i = 0; i < 8; i++)
#pragma unroll
            for (int j = 0; j < 4; j++) s[i][j] = 0.f;
#pragma unroll
        for (int kb = 0; kb < 8; kb++) {
#pragma unroll
            for (int nt = 0; nt < 8; nt++) {
                uint32_t b[2];
                int key = nt * 8 + (lane >> 2);
                b[0] = Ks[key * 68 + kb * 8 + (lane & 3)];
                b[1] = Ks[key * 68 + kb * 8 + (lane & 3) + 4];
                mma8(s[nt], qa[kb], b);
            }
        }

        if (kt == 16) {
#pragma unroll
            for (int nt = 0; nt < 8; nt++) {
                int col = kv0 + nt * 8 + 2 * (lane & 3);
                if (col >= SEQ_N)     { s[nt][0] = -1e30f; s[nt][2] = -1e30f; }
                if (col + 1 >= SEQ_N) { s[nt][1] = -1e30f; s[nt][3] = -1e30f; }
            }
        }

        // ---- online softmax ----
        float mx0 = -1e30f, mx1 = -1e30f;
#pragma unroll
        for (int nt = 0; nt < 8; nt++) {
            mx0 = fmaxf(mx0, fmaxf(s[nt][0], s[nt][1]));
            mx1 = fmaxf(mx1, fmaxf(s[nt][2], s[nt][3]));
        }
        mx0 = fmaxf(mx0, __shfl_xor_sync(0xffffffffu, mx0, 1));
        mx0 = fmaxf(mx0, __shfl_xor_sync(0xffffffffu, mx0, 2));
        mx1 = fmaxf(mx1, __shfl_xor_sync(0xffffffffu, mx1, 1));
        mx1 = fmaxf(mx1, __shfl_xor_sync(0xffffffffu, mx1, 2));
        float mn0 = fmaxf(m0r, mx0), mn1 = fmaxf(m1r, mx1);
        float cr0 = __expf(m0r - mn0), cr1 = __expf(m1r - mn1);
        float sum0 = 0.f, sum1 = 0.f;
#pragma unroll
        for (int nt = 0; nt < 8; nt++) {
            s[nt][0] = __expf(s[nt][0] - mn0);
            s[nt][1] = __expf(s[nt][1] - mn0);
            s[nt][2] = __expf(s[nt][2] - mn1);
            s[nt][3] = __expf(s[nt][3] - mn1);
            sum0 += s[nt][0] + s[nt][1];
            sum1 += s[nt][2] + s[nt][3];
        }
        sum0 += __shfl_xor_sync(0xffffffffu, sum0, 1);
        sum0 += __shfl_xor_sync(0xffffffffu, sum0, 2);
        sum1 += __shfl_xor_sync(0xffffffffu, sum1, 1);
        sum1 += __shfl_xor_sync(0xffffffffu, sum1, 2);
        l0 = l0 * cr0 + sum0;
        l1 = l1 * cr1 + sum1;
        m0r = mn0;
        m1r = mn1;
#pragma unroll
        for (int ne = 0; ne < 8; ne++) {
            of[ne][0] *= cr0; of[ne][1] *= cr0;
            of[ne][2] *= cr1; of[ne][3] *= cr1;
        }

        // ---- P -> warp-private strip ----
#pragma unroll
        for (int nt = 0; nt < 8; nt++) {
            int r = lane >> 2;
            int cc = nt * 8 + 2 * (lane & 3);
            Pw[r * 72 + cc]           = f2tf(s[nt][0]);
            Pw[r * 72 + cc + 1]       = f2tf(s[nt][1]);
            Pw[(r + 8) * 72 + cc]     = f2tf(s[nt][2]);
            Pw[(r + 8) * 72 + cc + 1] = f2tf(s[nt][3]);
        }
        __syncwarp();

        // ---- O += P V ----
#pragma unroll
        for (int kb = 0; kb < 8; kb++) {
            uint32_t pa[4];
            pa[0] = Pw[(lane >> 2) * 72 + kb * 8 + (lane & 3)];
            pa[1] = Pw[((lane >> 2) + 8) * 72 + kb * 8 + (lane & 3)];
            pa[2] = Pw[(lane >> 2) * 72 + kb * 8 + (lane & 3) + 4];
            pa[3] = Pw[((lane >> 2) + 8) * 72 + kb * 8 + (lane & 3) + 4];
#pragma unroll
            for (int ne = 0; ne < 8; ne++) {
                uint32_t b[2];
                int e = ne * 8 + (lane >> 2);
                b[0] = Vs[(kb * 8 + (lane & 3)) * 72 + e];
                b[1] = Vs[(kb * 8 + (lane & 3) + 4) * 72 + e];
                mma8(of[ne], pa, b);
            }
        }
        __syncwarp();
    }

    // ---- normalize + write context ----
    float inv0 = 1.f / l0, inv1 = 1.f / l1;
    const int hh = bh % NHEAD;
    const int bb = bh / NHEAD;
    const int qr0 = q0 + w * 16 + (lane >> 2);
    const int qr1 = qr0 + 8;
#pragma unroll
    for (int ne = 0; ne < 8; ne++) {
        int e = hh * 64 + ne * 8 + 2 * (lane & 3);
        if (qr0 < SEQ_N)
            *(float2*)&g_ctx[((size_t)(bb * SEQ_N + qr0)) * DMODEL + e] =
                make_float2(of[ne][0] * inv0, of[ne][1] * inv0);
        if (qr1 < SEQ_N)
            *(float2*)&g_ctx[((size_t)(bb * SEQ_N + qr1)) * DMODEL + e] =
                make_float2(of[ne][2] * inv1, of[ne][3] * inv1);
    }
}

// =================================================================
extern "C" void kernel_launch(void* const* d_in, const int* in_sizes, int n_in,
                              void* d_out, int out_size)
{
    const float* x     = (const float*)d_in[0];
    const float* Wqkv  = (const float*)d_in[1];
    const float* Wproj = (const float*)d_in[2];
    const float* bproj = (const float*)d_in[3];
    const float* freqs = (const float*)d_in[4];
    float* out = (float*)d_out;

    {
        dim3 grid((M_ROWS + 127) / 128, (3 * DMODEL) / 128);
        gemm_tc<0><<<grid, 256>>>(x, Wqkv, nullptr, nullptr, freqs);
    }
    {
        cudaFuncSetAttribute(attn_tc,
                             cudaFuncAttributeMaxDynamicSharedMemorySize,
                             ATTN_SMEM_BYTES);
        dim3 grid((SEQ_N + 127) / 128, NUM_B * NHEAD);
        attn_tc<<<grid, 256, ATTN_SMEM_BYTES>>>();
    }
    {
        dim3 grid((M_ROWS + 127) / 128, DMODEL / 128);
        gemm_tc<1><<<grid, 256>>>(nullptr, Wproj, out, bproj, nullptr);
    }
}

// round 7
// speedup vs baseline: 2.0100x; 1.1789x over previous
#include <cuda_runtime.h>
#include <cstdint>

#define NUM_B 16
#define SEQ_N 1025
#define NHEAD 12
#define HDIM  64
#define DMODEL 768
#define M_ROWS (NUM_B * SEQ_N)   // 16400

#define NX (M_ROWS * DMODEL)        // 12,595,200
#define NWQ (3 * DMODEL * DMODEL)   // 1,769,472
#define NWP (DMODEL * DMODEL)       // 589,824

// ---------------- scratch (tf32 bit patterns) ----------------
__device__ uint32_t g_xt[NX];
__device__ uint32_t g_wq[NWQ];
__device__ uint32_t g_wp[NWP];
__device__ uint32_t g_Q[NUM_B * NHEAD * SEQ_N * HDIM];
__device__ uint32_t g_K[NUM_B * NHEAD * SEQ_N * HDIM];
__device__ uint32_t g_V[NUM_B * NHEAD * SEQ_N * HDIM];
__device__ uint32_t g_ctx[NUM_B * SEQ_N * DMODEL];

__device__ __forceinline__ uint32_t f2tf(float f) {
    uint32_t r;
    asm("cvt.rna.tf32.f32 %0, %1;" : "=r"(r) : "f"(f));
    return r;
}
__device__ __forceinline__ void mma8(float* c, const uint32_t* a, const uint32_t* b) {
    asm volatile(
        "mma.sync.aligned.m16n8k8.row.col.f32.tf32.tf32.f32 "
        "{%0,%1,%2,%3}, {%4,%5,%6,%7}, {%8,%9}, {%0,%1,%2,%3};\n"
        : "+f"(c[0]), "+f"(c[1]), "+f"(c[2]), "+f"(c[3])
        : "r"(a[0]), "r"(a[1]), "r"(a[2]), "r"(a[3]), "r"(b[0]), "r"(b[1]));
}
__device__ __forceinline__ void cpa16(uint32_t dst, const void* src, int sz) {
    asm volatile("cp.async.cg.shared.global [%0], [%1], 16, %2;\n"
                 :: "r"(dst), "l"(src), "r"(sz));
}
__device__ __forceinline__ void cpa16u(uint32_t dst, const void* src) {
    asm volatile("cp.async.cg.shared.global [%0], [%1], 16;\n"
                 :: "r"(dst), "l"(src));
}
#define CPA_COMMIT() asm volatile("cp.async.commit_group;\n")
#define CPA_WAIT0()  asm volatile("cp.async.wait_group 0;\n")

// ---------------- prepass: fp32 -> tf32 bits ----------------
__global__ void prep_tf32(const float* __restrict__ src, uint32_t* __restrict__ dst, int n4)
{
    int i = blockIdx.x * blockDim.x + threadIdx.x;
    if (i < n4) {
        float4 v = *(const float4*)&src[i * 4];
        uint4 u;
        u.x = f2tf(v.x); u.y = f2tf(v.y); u.z = f2tf(v.z); u.w = f2tf(v.w);
        *(uint4*)&dst[i * 4] = u;
    }
}

// =================================================================
// TN GEMM, tf32 TC, cp.async 2-stage. Block 128x128, 256 thr,
// 8 warps (4m x 2n), warp tile 32x64, k-step 32, XOR-swizzled smem.
// Dynamic smem: As[2][4096] | Bs[2][4096] = 64 KB.
// MODE 0: RoPE epilogue -> g_Q/g_K/g_V (tf32 bits, Q pre-scaled).
// MODE 1: +bias -> out (fp32).
// =================================================================
#define GEMM_SMEM_BYTES (16384 * 4)

template<int MODE>
__global__ __launch_bounds__(256, 2) void gemm_tc(
    float* __restrict__ out, const float* __restrict__ bias,
    const float* __restrict__ freqs)
{
    extern __shared__ uint32_t gsm[];
    uint32_t* Asm = gsm;            // [2][4096]
    uint32_t* Bsm = gsm + 8192;     // [2][4096]

    const int tid = threadIdx.x;
    const int lane = tid & 31;
    const int wid = tid >> 5;
    const int wm = wid & 3;
    const int wn = wid >> 2;
    const int m0 = blockIdx.x * 128;
    const int n0 = blockIdx.y * 128;

    const uint32_t* Ag = (MODE == 1) ? g_ctx : g_xt;
    const uint32_t* Bg = (MODE == 1) ? g_wp : g_wq;

    const uint32_t aAddr = (uint32_t)__cvta_generic_to_shared(Asm);
    const uint32_t bAddr = (uint32_t)__cvta_generic_to_shared(Bsm);

    float c[2][8][4];
#pragma unroll
    for (int i = 0; i < 2; i++)
#pragma unroll
        for (int j = 0; j < 8; j++)
#pragma unroll
            for (int r = 0; r < 4; r++) c[i][j][r] = 0.f;

    const int rowL = tid >> 3;          // 0..31
    const int col4 = tid & 7;           // k chunk 0..7
    const int s7 = lane >> 2;
    const int l3 = lane & 3;

    auto stage_ld = [&](int k0, int s) {
#pragma unroll
        for (int p = 0; p < 4; p++) {
            int m = rowL + p * 32;
            int gm = m0 + m;
            int sz = (gm < M_ROWS) ? 16 : 0;
            cpa16(aAddr + (s * 4096 + m * 32 + ((col4 ^ (m & 7)) << 2)) * 4,
                  &Ag[(size_t)gm * DMODEL + k0 + col4 * 4], sz);
        }
#pragma unroll
        for (int p = 0; p < 4; p++) {
            int n = rowL + p * 32;
            cpa16u(bAddr + (s * 4096 + n * 32 + ((col4 ^ (n & 7)) << 2)) * 4,
                   &Bg[(size_t)(n0 + n) * DMODEL + k0 + col4 * 4]);
        }
        CPA_COMMIT();
    };

    stage_ld(0, 0);
    int stage = 0;
    for (int k0 = 0; k0 < DMODEL; k0 += 32) {
        CPA_WAIT0();
        __syncthreads();
        if (k0 + 32 < DMODEL) stage_ld(k0 + 32, stage ^ 1);

        const uint32_t* Ab = Asm + stage * 4096;
        const uint32_t* Bb = Bsm + stage * 4096;
#pragma unroll
        for (int kb = 0; kb < 4; kb++) {
            const int pc0 = (((2 * kb)     ^ s7) << 2) + l3;
            const int pc1 = (((2 * kb + 1) ^ s7) << 2) + l3;
            uint32_t a[2][4], b[8][2];
#pragma unroll
            for (int mt = 0; mt < 2; mt++) {
                int mr = wm * 32 + mt * 16 + s7;
                a[mt][0] = Ab[mr * 32 + pc0];
                a[mt][1] = Ab[(mr + 8) * 32 + pc0];
                a[mt][2] = Ab[mr * 32 + pc1];
                a[mt][3] = Ab[(mr + 8) * 32 + pc1];
            }
#pragma unroll
            for (int nt = 0; nt < 8; nt++) {
                int nc = wn * 64 + nt * 8 + s7;
                b[nt][0] = Bb[nc * 32 + pc0];
                b[nt][1] = Bb[nc * 32 + pc1];
            }
#pragma unroll
            for (int mt = 0; mt < 2; mt++)
#pragma unroll
                for (int nt = 0; nt < 8; nt++)
                    mma8(c[mt][nt], a[mt], b[nt]);
        }
        stage ^= 1;
    }

    // -------- epilogue --------
    if (MODE == 0) {
        const int sidx = n0 / DMODEL;
        const int hh = ((n0 % DMODEL) >> 6) + wn;
        uint32_t* dst = (sidx == 0) ? g_Q : (sidx == 1) ? g_K : g_V;
        const float qscale = (sidx == 0) ? 0.125f : 1.0f;
#pragma unroll
        for (int nt = 0; nt < 8; nt++) {
            int e0 = nt * 8 + 2 * l3;
            float f0 = 0.f, f1 = 0.f;
            if (sidx < 2) {
                int fi = hh * 32 + (e0 >> 1);
                f0 = freqs[fi];
                f1 = freqs[384 + fi];
            }
#pragma unroll
            for (int mt = 0; mt < 2; mt++)
#pragma unroll
                for (int hr = 0; hr < 2; hr++) {
                    int row = m0 + wm * 32 + mt * 16 + s7 + hr * 8;
                    if (row >= M_ROWS) continue;
                    int bb = row / SEQ_N;
                    int n = row - bb * SEQ_N;
                    float v0 = c[mt][nt][hr * 2 + 0];
                    float v1 = c[mt][nt][hr * 2 + 1];
                    if (sidx < 2 && n >= 1) {
                        int t = n - 1;
                        float ang = (float)(t & 31) * f0 + (float)(t >> 5) * f1;
                        float sn, cs;
                        sincosf(ang, &sn, &cs);
                        float a0 = v0, b0 = v1;
                        v0 = a0 * cs - b0 * sn;
                        v1 = a0 * sn + b0 * cs;
                    }
                    size_t off = ((size_t)((bb * NHEAD + hh) * SEQ_N + n)) * HDIM + e0;
                    uint2 u;
                    u.x = f2tf(v0 * qscale);
                    u.y = f2tf(v1 * qscale);
                    *(uint2*)&dst[off] = u;
                }
        }
    } else {
#pragma unroll
        for (int nt = 0; nt < 8; nt++) {
            int col = n0 + wn * 64 + nt * 8 + 2 * l3;
            float b0v = bias[col], b1v = bias[col + 1];
#pragma unroll
            for (int mt = 0; mt < 2; mt++)
#pragma unroll
                for (int hr = 0; hr < 2; hr++) {
                    int row = m0 + wm * 32 + mt * 16 + s7 + hr * 8;
                    if (row >= M_ROWS) continue;
                    *(float2*)&out[(size_t)row * DMODEL + col] =
                        make_float2(c[mt][nt][hr * 2 + 0] + b0v,
                                    c[mt][nt][hr * 2 + 1] + b1v);
                }
        }
    }
}

// =================================================================
// Flash attention, tf32 TC, cp.async double-buffered K/V.
// 256 threads (8 warps), 128 q/block, 16 q/warp, kv tiles of 64.
// KV buf: [2] x (Ks 64x68 | Vs 64x72) = 2x8960 u32; P strips 8x16x72.
// =================================================================
#define KV_STRIDE 8960
#define ATTN_SMEM_BYTES ((2 * KV_STRIDE + 8 * 16 * 72) * 4)   // 108544

__global__ __launch_bounds__(256, 2) void attn_tc()
{
    extern __shared__ uint32_t dsm[];
    uint32_t* Ps = dsm + 2 * KV_STRIDE;

    const int tid = threadIdx.x;
    const int lane = tid & 31;
    const int w = tid >> 5;
    const int q0 = blockIdx.x * 128;
    const int bh = blockIdx.y;
    const size_t base = (size_t)bh * SEQ_N * HDIM;
    uint32_t* Pw = Ps + w * 16 * 72;

    const uint32_t smBase = (uint32_t)__cvta_generic_to_shared(dsm);
    const uint32_t pwAddr = (uint32_t)__cvta_generic_to_shared(Pw);

    auto issue_kv = [&](int kt, int s) {
        const int kv0 = kt * 64;
        const uint32_t bufA = smBase + s * KV_STRIDE * 4;
#pragma unroll
        for (int it = 0; it < 4; it++) {
            int slot = tid + it * 256;
            int r = slot >> 4;
            int cg = (slot & 15) * 4;
            int gk = kv0 + r;
            int sz = (gk < SEQ_N) ? 16 : 0;
            size_t off = base + (size_t)gk * HDIM + cg;
            cpa16(bufA + (r * 68 + cg) * 4, &g_K[off], sz);
            cpa16(bufA + (4352 + r * 72 + cg) * 4, &g_V[off], sz);
        }
        CPA_COMMIT();
    };

    // ---- stage Q (pre-scaled tf32 bits) into strip ----
#pragma unroll
    for (int it = 0; it < 8; it++) {
        int slot = lane + it * 32;
        int r = slot >> 4;
        int cg = (slot & 15) * 4;
        int gq = q0 + w * 16 + r;
        int sz = (gq < SEQ_N) ? 16 : 0;
        cpa16(pwAddr + (r * 72 + cg) * 4, &g_Q[base + (size_t)gq * HDIM + cg], sz);
    }
    CPA_COMMIT();
    CPA_WAIT0();
    __syncwarp();
    uint32_t qa[8][4];
#pragma unroll
    for (int kb = 0; kb < 8; kb++) {
        qa[kb][0] = Pw[(lane >> 2) * 72 + kb * 8 + (lane & 3)];
        qa[kb][1] = Pw[((lane >> 2) + 8) * 72 + kb * 8 + (lane & 3)];
        qa[kb][2] = Pw[(lane >> 2) * 72 + kb * 8 + (lane & 3) + 4];
        qa[kb][3] = Pw[((lane >> 2) + 8) * 72 + kb * 8 + (lane & 3) + 4];
    }
    __syncwarp();

    float of[8][4];
#pragma unroll
    for (int i = 0; i < 8; i++)
#pragma unroll
        for (int j = 0; j < 4; j++) of[i][j] = 0.f;
    float m0r = -1e30f, m1r = -1e30f, l0 = 0.f, l1 = 0.f;

    issue_kv(0, 0);
    int stage = 0;

    for (int kt = 0; kt < 17; kt++) {
        const int kv0 = kt * 64;
        CPA_WAIT0();
        __syncthreads();
        if (kt + 1 < 17) issue_kv(kt + 1, stage ^ 1);

        const uint32_t* Ks = dsm + stage * KV_STRIDE;
        const uint32_t* Vs = Ks + 4352;

        // ---- S = Q K^T ----
        float s[8][4];
#pragma unroll
        for (int i = 0; i < 8; i++)
#pragma unroll
            for (int j = 0; j < 4; j++) s[i][j] = 0.f;
#pragma unroll
        for (int kb = 0; kb < 8; kb++) {
#pragma unroll
            for (int nt = 0; nt < 8; nt++) {
                uint32_t b[2];
                int key = nt * 8 + (lane >> 2);
                b[0] = Ks[key * 68 + kb * 8 + (lane & 3)];
                b[1] = Ks[key * 68 + kb * 8 + (lane & 3) + 4];
                mma8(s[nt], qa[kb], b);
            }
        }

        if (kt == 16) {
#pragma unroll
            for (int nt = 0; nt < 8; nt++) {
                int col = kv0 + nt * 8 + 2 * (lane & 3);
                if (col >= SEQ_N)     { s[nt][0] = -1e30f; s[nt][2] = -1e30f; }
                if (col + 1 >= SEQ_N) { s[nt][1] = -1e30f; s[nt][3] = -1e30f; }
            }
        }

        // ---- online softmax ----
        float mx0 = -1e30f, mx1 = -1e30f;
#pragma unroll
        for (int nt = 0; nt < 8; nt++) {
            mx0 = fmaxf(mx0, fmaxf(s[nt][0], s[nt][1]));
            mx1 = fmaxf(mx1, fmaxf(s[nt][2], s[nt][3]));
        }
        mx0 = fmaxf(mx0, __shfl_xor_sync(0xffffffffu, mx0, 1));
        mx0 = fmaxf(mx0, __shfl_xor_sync(0xffffffffu, mx0, 2));
        mx1 = fmaxf(mx1, __shfl_xor_sync(0xffffffffu, mx1, 1));
        mx1 = fmaxf(mx1, __shfl_xor_sync(0xffffffffu, mx1, 2));
        float mn0 = fmaxf(m0r, mx0), mn1 = fmaxf(m1r, mx1);
        float cr0 = __expf(m0r - mn0), cr1 = __expf(m1r - mn1);
        float sum0 = 0.f, sum1 = 0.f;
#pragma unroll
        for (int nt = 0; nt < 8; nt++) {
            s[nt][0] = __expf(s[nt][0] - mn0);
            s[nt][1] = __expf(s[nt][1] - mn0);
            s[nt][2] = __expf(s[nt][2] - mn1);
            s[nt][3] = __expf(s[nt][3] - mn1);
            sum0 += s[nt][0] + s[nt][1];
            sum1 += s[nt][2] + s[nt][3];
        }
        sum0 += __shfl_xor_sync(0xffffffffu, sum0, 1);
        sum0 += __shfl_xor_sync(0xffffffffu, sum0, 2);
        sum1 += __shfl_xor_sync(0xffffffffu, sum1, 1);
        sum1 += __shfl_xor_sync(0xffffffffu, sum1, 2);
        l0 = l0 * cr0 + sum0;
        l1 = l1 * cr1 + sum1;
        m0r = mn0;
        m1r = mn1;
#pragma unroll
        for (int ne = 0; ne < 8; ne++) {
            of[ne][0] *= cr0; of[ne][1] *= cr0;
            of[ne][2] *= cr1; of[ne][3] *= cr1;
        }

        // ---- P -> warp-private strip ----
#pragma unroll
        for (int nt = 0; nt < 8; nt++) {
            int r = lane >> 2;
            int cc = nt * 8 + 2 * (lane & 3);
            Pw[r * 72 + cc]           = f2tf(s[nt][0]);
            Pw[r * 72 + cc + 1]       = f2tf(s[nt][1]);
            Pw[(r + 8) * 72 + cc]     = f2tf(s[nt][2]);
            Pw[(r + 8) * 72 + cc + 1] = f2tf(s[nt][3]);
        }
        __syncwarp();

        // ---- O += P V ----
#pragma unroll
        for (int kb = 0; kb < 8; kb++) {
            uint32_t pa[4];
            pa[0] = Pw[(lane >> 2) * 72 + kb * 8 + (lane & 3)];
            pa[1] = Pw[((lane >> 2) + 8) * 72 + kb * 8 + (lane & 3)];
            pa[2] = Pw[(lane >> 2) * 72 + kb * 8 + (lane & 3) + 4];
            pa[3] = Pw[((lane >> 2) + 8) * 72 + kb * 8 + (lane & 3) + 4];
#pragma unroll
            for (int ne = 0; ne < 8; ne++) {
                uint32_t b[2];
                int e = ne * 8 + (lane >> 2);
                b[0] = Vs[(kb * 8 + (lane & 3)) * 72 + e];
                b[1] = Vs[(kb * 8 + (lane & 3) + 4) * 72 + e];
                mma8(of[ne], pa, b);
            }
        }
        __syncwarp();
        stage ^= 1;
    }

    // ---- normalize + write context (tf32 bits) ----
    float inv0 = 1.f / l0, inv1 = 1.f / l1;
    const int hh = bh % NHEAD;
    const int bb = bh / NHEAD;
    const int qr0 = q0 + w * 16 + (lane >> 2);
    const int qr1 = qr0 + 8;
#pragma unroll
    for (int ne = 0; ne < 8; ne++) {
        int e = hh * 64 + ne * 8 + 2 * (lane & 3);
        if (qr0 < SEQ_N) {
            uint2 u;
            u.x = f2tf(of[ne][0] * inv0);
            u.y = f2tf(of[ne][1] * inv0);
            *(uint2*)&g_ctx[((size_t)(bb * SEQ_N + qr0)) * DMODEL + e] = u;
        }
        if (qr1 < SEQ_N) {
            uint2 u;
            u.x = f2tf(of[ne][2] * inv1);
            u.y = f2tf(of[ne][3] * inv1);
            *(uint2*)&g_ctx[((size_t)(bb * SEQ_N + qr1)) * DMODEL + e] = u;
        }
    }
}

// =================================================================
extern "C" void kernel_launch(void* const* d_in, const int* in_sizes, int n_in,
                              void* d_out, int out_size)
{
    const float* x     = (const float*)d_in[0];
    const float* Wqkv  = (const float*)d_in[1];
    const float* Wproj = (const float*)d_in[2];
    const float* bproj = (const float*)d_in[3];
    const float* freqs = (const float*)d_in[4];
    float* out = (float*)d_out;

    uint32_t* xt;  cudaGetSymbolAddress((void**)&xt, g_xt);
    uint32_t* wq;  cudaGetSymbolAddress((void**)&wq, g_wq);
    uint32_t* wp;  cudaGetSymbolAddress((void**)&wp, g_wp);

    cudaFuncSetAttribute(gemm_tc<0>, cudaFuncAttributeMaxDynamicSharedMemorySize,
                         GEMM_SMEM_BYTES);
    cudaFuncSetAttribute(gemm_tc<1>, cudaFuncAttributeMaxDynamicSharedMemorySize,
                         GEMM_SMEM_BYTES);
    cudaFuncSetAttribute(attn_tc, cudaFuncAttributeMaxDynamicSharedMemorySize,
                         ATTN_SMEM_BYTES);

    // 0) prepass: fp32 -> tf32 bits
    prep_tf32<<<(NX / 4 + 255) / 256, 256>>>(x, xt, NX / 4);
    prep_tf32<<<(NWQ / 4 + 255) / 256, 256>>>(Wqkv, wq, NWQ / 4);
    prep_tf32<<<(NWP / 4 + 255) / 256, 256>>>(Wproj, wp, NWP / 4);

    // 1) QKV GEMM + fused RoPE
    {
        dim3 grid((M_ROWS + 127) / 128, (3 * DMODEL) / 128);
        gemm_tc<0><<<grid, 256, GEMM_SMEM_BYTES>>>(nullptr, nullptr, freqs);
    }
    // 2) attention
    {
        dim3 grid((SEQ_N + 127) / 128, NUM_B * NHEAD);
        attn_tc<<<grid, 256, ATTN_SMEM_BYTES>>>();
    }
    // 3) proj GEMM + bias
    {
        dim3 grid((M_ROWS + 127) / 128, DMODEL / 128);
        gemm_tc<1><<<grid, 256, GEMM_SMEM_BYTES>>>(out, bproj, nullptr);
    }
}

// round 8
// speedup vs baseline: 2.1246x; 1.0570x over previous
#include <cuda_runtime.h>
#include <cstdint>

#define NUM_B 16
#define SEQ_N 1025
#define NHEAD 12
#define HDIM  64
#define DMODEL 768
#define M_ROWS 16400
#define NBH (NUM_B * NHEAD)       // 192

// ---- packed geometry ----
#define A_MG   1025               // m-groups of 16 (16400 = 1025*16)
#define KG_D   96                 // 768/8
#define APK_SZ (A_MG * KG_D * 128)      // 12,595,200 u32
#define WQ_NG  288                // 2304/8
#define WP_NG  96                 // 768/8
#define Q_QG   65                 // ceil(1025/16)
#define QBUF_BH (Q_QG * 8 * 128)        // 66560 u32 (= 65*1024)
#define KBUF_BH (136 * 8 * 64)          // 69632 u32 (keys padded to 1088)

// ---------------- scratch (tf32 bit patterns, packed) ----------------
__device__ uint32_t g_xt[APK_SZ];
__device__ uint32_t g_ctxp[APK_SZ];
__device__ uint32_t g_wq[WQ_NG * KG_D * 64];
__device__ uint32_t g_wp[WP_NG * KG_D * 64];
__device__ uint32_t g_Q[NBH * QBUF_BH];
__device__ uint32_t g_K[NBH * KBUF_BH];
__device__ uint32_t g_V[NBH * KBUF_BH];

__device__ __forceinline__ uint32_t f2tf(float f) {
    uint32_t r;
    asm("cvt.rna.tf32.f32 %0, %1;" : "=r"(r) : "f"(f));
    return r;
}
__device__ __forceinline__ void mma8(float* c, const uint32_t* a, const uint32_t* b) {
    asm volatile(
        "mma.sync.aligned.m16n8k8.row.col.f32.tf32.tf32.f32 "
        "{%0,%1,%2,%3}, {%4,%5,%6,%7}, {%8,%9}, {%0,%1,%2,%3};\n"
        : "+f"(c[0]), "+f"(c[1]), "+f"(c[2]), "+f"(c[3])
        : "r"(a[0]), "r"(a[1]), "r"(a[2]), "r"(a[3]), "r"(b[0]), "r"(b[1]));
}
__device__ __forceinline__ void cpa16(uint32_t dst, const void* src, int sz) {
    asm volatile("cp.async.cg.shared.global [%0], [%1], 16, %2;\n"
                 :: "r"(dst), "l"(src), "r"(sz));
}
__device__ __forceinline__ void cpa16u(uint32_t dst, const void* src) {
    asm volatile("cp.async.cg.shared.global [%0], [%1], 16;\n"
                 :: "r"(dst), "l"(src));
}
#define CPA_COMMIT() asm volatile("cp.async.commit_group;\n")
#define CPA_WAIT0()  asm volatile("cp.async.wait_group 0;\n")
#define CPA_WAIT1()  asm volatile("cp.async.wait_group 1;\n")

// ---------------- prepass: pack fp32 -> tf32 bits in frag layouts ----------------
// A layout: [m>>4][k>>3][ (m&7)*16 + (k&3)*4 + ((m>>3)&1) + 2*((k>>2)&1) ]
__global__ void pack_a(const float* __restrict__ src, uint32_t* __restrict__ dst, int n)
{
    int id = blockIdx.x * 256 + threadIdx.x;     // per (m, k-chunk4)
    if (id >= n) return;
    int m = id / 192;
    int c = id - m * 192;                        // k chunk: k = 4c..4c+3
    float4 v = *(const float4*)&src[(size_t)m * DMODEL + c * 4];
    uint32_t* p = &dst[((size_t)(m >> 4) * KG_D + (c >> 1)) * 128
                       + (m & 7) * 16 + ((m >> 3) & 1) + 2 * (c & 1)];
    p[0]  = f2tf(v.x);
    p[4]  = f2tf(v.y);
    p[8]  = f2tf(v.z);
    p[12] = f2tf(v.w);
}
// B layout: [n>>3][k>>3][ (n&7)*8 + (k&3)*2 + ((k>>2)&1) ]
__global__ void pack_w(const float* __restrict__ src, uint32_t* __restrict__ dst, int n)
{
    int id = blockIdx.x * 256 + threadIdx.x;     // per (row n, k-chunk4)
    if (id >= n) return;
    int nn = id / 192;
    int c = id - nn * 192;
    float4 v = *(const float4*)&src[(size_t)nn * DMODEL + c * 4];
    uint32_t* p = &dst[((size_t)(nn >> 3) * KG_D + (c >> 1)) * 64
                       + (nn & 7) * 8 + (c & 1)];
    p[0] = f2tf(v.x);
    p[2] = f2tf(v.y);
    p[4] = f2tf(v.z);
    p[6] = f2tf(v.w);
}
// zero K/V pad (keys 1024..1087 region; valid key 1024 rewritten later)
__global__ void zero_pad()
{
    int id = blockIdx.x * 256 + threadIdx.x;
    if (id >= NBH * 4096) return;
    int bh = id >> 12;
    int i = id & 4095;
    g_K[(size_t)bh * KBUF_BH + 65536 + i] = 0;
    g_V[(size_t)bh * KBUF_BH + 65536 + i] = 0;
}

// =================================================================
// TN GEMM, tf32 TC, 3-stage cp.async, packed-fragment smem.
// Block 128x128, 256 thr, 8 warps (4m x 2n), warp 32x64, k-step 32.
// Per stage: A 4096 u32 | B 4096 u32. 3 stages = 96 KB.
// MODE 0: RoPE epilogue -> g_Q/g_K/g_V packed. MODE 1: +bias -> out.
// =================================================================
#define GEMM_SMEM_BYTES (3 * 8192 * 4)

template<int MODE>
__global__ __launch_bounds__(256, 2) void gemm_tc(
    float* __restrict__ out, const float* __restrict__ bias,
    const float* __restrict__ freqs)
{
    extern __shared__ uint32_t gsm[];

    const int tid = threadIdx.x;
    const int lane = tid & 31;
    const int wid = tid >> 5;
    const int wm = wid & 3;
    const int wn = wid >> 2;
    const int m0 = blockIdx.x * 128;
    const int n0 = blockIdx.y * 128;

    const uint32_t* Ag = (MODE == 1) ? g_ctxp : g_xt;
    const uint32_t* Bg = (MODE == 1) ? g_wp : g_wq;

    const uint32_t smAddr = (uint32_t)__cvta_generic_to_shared(gsm);

    float c[2][8][4];
#pragma unroll
    for (int i = 0; i < 2; i++)
#pragma unroll
        for (int j = 0; j < 8; j++)
#pragma unroll
            for (int r = 0; r < 4; r++) c[i][j][r] = 0.f;

    const int s7 = lane >> 2;
    const int l3 = lane & 3;
    const int mg0 = m0 >> 4;
    const int ng0 = n0 >> 3;

    auto stage_ld = [&](int k0, int s) {
        const int kg0 = k0 >> 3;
        // A: 1024 chunks of 16B (32 blocks x 128 u32)
#pragma unroll
        for (int it = 0; it < 4; it++) {
            int ch = tid + it * 256;
            int blk = ch >> 5;                 // 0..31: mb = blk>>2, kb = blk&3
            int inner = (ch & 31) * 4;
            int mg = mg0 + (blk >> 2);
            int sz = (mg < A_MG) ? 16 : 0;
            cpa16(smAddr + (s * 8192 + blk * 128 + inner) * 4,
                  &Ag[((size_t)mg * KG_D + kg0 + (blk & 3)) * 128 + inner], sz);
        }
        // B: 1024 chunks (64 blocks x 64 u32)
#pragma unroll
        for (int it = 0; it < 4; it++) {
            int ch = tid + it * 256;
            int blk = ch >> 4;                 // 0..63: nb = blk>>2, kb = blk&3
            int inner = (ch & 15) * 4;
            int ng = ng0 + (blk >> 2);
            cpa16u(smAddr + (s * 8192 + 4096 + blk * 64 + inner) * 4,
                   &Bg[((size_t)ng * KG_D + kg0 + (blk & 3)) * 64 + inner]);
        }
        CPA_COMMIT();
    };

    stage_ld(0, 0);
    stage_ld(32, 1);

    int stage = 0;
    for (int k0 = 0; k0 < DMODEL; k0 += 32) {
        if (k0 + 32 < DMODEL) CPA_WAIT1(); else CPA_WAIT0();
        __syncthreads();
        if (k0 + 64 < DMODEL) stage_ld(k0 + 64, stage == 0 ? 2 : stage - 1);

        const uint32_t* Ab = gsm + stage * 8192;
        const uint32_t* Bb = Ab + 4096;
#pragma unroll
        for (int kb = 0; kb < 4; kb++) {
            uint32_t a[2][4], b[8][2];
#pragma unroll
            for (int mt = 0; mt < 2; mt++) {
                uint4 av = *(const uint4*)&Ab[(((wm * 2 + mt) * 4 + kb) << 7) + lane * 4];
                a[mt][0] = av.x; a[mt][1] = av.y; a[mt][2] = av.z; a[mt][3] = av.w;
            }
#pragma unroll
            for (int nt = 0; nt < 8; nt++) {
                uint2 bv = *(const uint2*)&Bb[(((wn * 8 + nt) * 4 + kb) << 6) + lane * 2];
                b[nt][0] = bv.x; b[nt][1] = bv.y;
            }
#pragma unroll
            for (int mt = 0; mt < 2; mt++)
#pragma unroll
                for (int nt = 0; nt < 8; nt++)
                    mma8(c[mt][nt], a[mt], b[nt]);
        }
        stage = (stage == 2) ? 0 : stage + 1;
    }

    // -------- epilogue --------
    if (MODE == 0) {
        const int sidx = n0 / DMODEL;                 // 0=Q 1=K 2=V (uniform/block)
        const int hh = ((n0 % DMODEL) >> 6) + wn;     // head (uniform/warp)
        const float qscale = (sidx == 0) ? 0.125f : 1.0f;
#pragma unroll
        for (int nt = 0; nt < 8; nt++) {
            int e0 = nt * 8 + 2 * l3;
            float f0 = 0.f, f1 = 0.f;
            if (sidx < 2) {
                int fi = hh * 32 + (e0 >> 1);
                f0 = freqs[fi];
                f1 = freqs[384 + fi];
            }
#pragma unroll
            for (int mt = 0; mt < 2; mt++)
#pragma unroll
                for (int hr = 0; hr < 2; hr++) {
                    int row = m0 + wm * 32 + mt * 16 + s7 + hr * 8;
                    if (row >= M_ROWS) continue;
                    int bb = row / SEQ_N;
                    int n = row - bb * SEQ_N;          // token (q or key)
                    float v0 = c[mt][nt][hr * 2 + 0];
                    float v1 = c[mt][nt][hr * 2 + 1];
                    if (sidx < 2 && n >= 1) {
                        int t = n - 1;
                        float ang = (float)(t & 31) * f0 + (float)(t >> 5) * f1;
                        float sn, cs;
                        sincosf(ang, &sn, &cs);
                        float a0 = v0, b0 = v1;
                        v0 = a0 * cs - b0 * sn;
                        v1 = a0 * sn + b0 * cs;
                    }
                    int bh = bb * NHEAD + hh;
                    if (sidx == 0) {
                        size_t pos = (size_t)bh * QBUF_BH
                            + ((size_t)(n >> 4) * 8 + (e0 >> 3)) * 128
                            + (n & 7) * 16 + (e0 & 3) * 4 + ((n >> 3) & 1)
                            + 2 * ((e0 >> 2) & 1);
                        g_Q[pos]     = f2tf(v0 * qscale);
                        g_Q[pos + 4] = f2tf(v1 * qscale);
                    } else if (sidx == 1) {
                        size_t pos = (size_t)bh * KBUF_BH
                            + ((size_t)(n >> 3) * 8 + (e0 >> 3)) * 64
                            + (n & 7) * 8 + (e0 & 3) * 2 + ((e0 >> 2) & 1);
                        g_K[pos]     = f2tf(v0);
                        g_K[pos + 2] = f2tf(v1);
                    } else {
                        size_t pos = (size_t)bh * KBUF_BH
                            + ((size_t)(n >> 3) * 8 + (e0 >> 3)) * 64
                            + (e0 & 7) * 8 + (n & 3) * 2 + ((n >> 2) & 1);
                        g_V[pos]     = f2tf(v0);
                        g_V[pos + 8] = f2tf(v1);
                    }
                }
        }
    } else {
#pragma unroll
        for (int nt = 0; nt < 8; nt++) {
            int col = n0 + wn * 64 + nt * 8 + 2 * l3;
            float b0v = bias[col], b1v = bias[col + 1];
#pragma unroll
            for (int mt = 0; mt < 2; mt++)
#pragma unroll
                for (int hr = 0; hr < 2; hr++) {
                    int row = m0 + wm * 32 + mt * 16 + s7 + hr * 8;
                    if (row >= M_ROWS) continue;
                    *(float2*)&out[(size_t)row * DMODEL + col] =
                        make_float2(c[mt][nt][hr * 2 + 0] + b0v,
                                    c[mt][nt][hr * 2 + 1] + b1v);
                }
        }
    }
}

// =================================================================
// Flash attention, tf32 TC, packed frags, cp.async 2-stage K/V.
// 256 threads (8 warps), 128 q/block, 16 q/warp, kv tiles of 64.
// smem: KV 2 x 8192 u32 | P strips 8 x 1152 u32 = 102400 B.
// K tile = V tile = 4096 u32, gmem-contiguous per tile.
// =================================================================
#define ATTN_SMEM_BYTES ((2 * 8192 + 8 * 1152) * 4)

__global__ __launch_bounds__(256, 2) void attn_tc()
{
    extern __shared__ uint32_t dsm[];
    uint32_t* Ps = dsm + 2 * 8192;

    const int tid = threadIdx.x;
    const int lane = tid & 31;
    const int w = tid >> 5;
    const int bx = blockIdx.x;
    const int q0 = bx * 128;
    const int bh = blockIdx.y;
    uint32_t* Pw = Ps + w * 1152;

    const uint32_t* Kg = g_K + (size_t)bh * KBUF_BH;
    const uint32_t* Vg = g_V + (size_t)bh * KBUF_BH;

    const uint32_t smBase = (uint32_t)__cvta_generic_to_shared(dsm);
    const uint32_t pwAddr = (uint32_t)__cvta_generic_to_shared(Pw);

    auto issue_kv = [&](int kt, int s) {
        const uint32_t buf = smBase + s * 8192 * 4;
        const uint32_t* ks = Kg + kt * 4096;
        const uint32_t* vs = Vg + kt * 4096;
#pragma unroll
        for (int it = 0; it < 4; it++) {
            int ch = tid + it * 256;
            cpa16u(buf + ch * 16, ks + ch * 4);
            cpa16u(buf + 16384 + ch * 16, vs + ch * 4);
        }
        CPA_COMMIT();
    };

    // ---- stage Q (packed A-frag, pre-scaled) into strip, then regs ----
    {
        int qg = bx * 8 + w;
        int sz = (qg < Q_QG) ? 16 : 0;
        const uint32_t* qs = g_Q + (size_t)bh * QBUF_BH + (size_t)qg * 1024;
#pragma unroll
        for (int it = 0; it < 8; it++) {
            int ch = lane + it * 32;
            cpa16(pwAddr + ch * 16, qs + ch * 4, sz);
        }
        CPA_COMMIT();
        CPA_WAIT0();
        __syncwarp();
    }
    uint32_t qa[8][4];
#pragma unroll
    for (int kb = 0; kb < 8; kb++) {
        uint4 qv = *(const uint4*)&Pw[(kb << 7) + lane * 4];
        qa[kb][0] = qv.x; qa[kb][1] = qv.y; qa[kb][2] = qv.z; qa[kb][3] = qv.w;
    }
    __syncwarp();

    float of[8][4];
#pragma unroll
    for (int i = 0; i < 8; i++)
#pragma unroll
        for (int j = 0; j < 4; j++) of[i][j] = 0.f;
    float m0r = -1e30f, m1r = -1e30f, l0 = 0.f, l1 = 0.f;

    issue_kv(0, 0);
    int stage = 0;

    for (int kt = 0; kt < 17; kt++) {
        const int kv0 = kt * 64;
        CPA_WAIT0();
        __syncthreads();
        if (kt + 1 < 17) issue_kv(kt + 1, stage ^ 1);

        const uint32_t* Ks = dsm + stage * 8192;
        const uint32_t* Vs = Ks + 4096;

        // ---- S = Q K^T ----
        float s[8][4];
#pragma unroll
        for (int i = 0; i < 8; i++)
#pragma unroll
            for (int j = 0; j < 4; j++) s[i][j] = 0.f;
#pragma unroll
        for (int kb = 0; kb < 8; kb++) {
#pragma unroll
            for (int nt = 0; nt < 8; nt++) {
                uint2 bv = *(const uint2*)&Ks[((nt * 8 + kb) << 6) + lane * 2];
                uint32_t b[2] = {bv.x, bv.y};
                mma8(s[nt], qa[kb], b);
            }
        }

        if (kt == 16) {
#pragma unroll
            for (int nt = 0; nt < 8; nt++) {
                int col = kv0 + nt * 8 + 2 * (lane & 3);
                if (col >= SEQ_N)     { s[nt][0] = -1e30f; s[nt][2] = -1e30f; }
                if (col + 1 >= SEQ_N) { s[nt][1] = -1e30f; s[nt][3] = -1e30f; }
            }
        }

        // ---- online softmax ----
        float mx0 = -1e30f, mx1 = -1e30f;
#pragma unroll
        for (int nt = 0; nt < 8; nt++) {
            mx0 = fmaxf(mx0, fmaxf(s[nt][0], s[nt][1]));
            mx1 = fmaxf(mx1, fmaxf(s[nt][2], s[nt][3]));
        }
        mx0 = fmaxf(mx0, __shfl_xor_sync(0xffffffffu, mx0, 1));
        mx0 = fmaxf(mx0, __shfl_xor_sync(0xffffffffu, mx0, 2));
        mx1 = fmaxf(mx1, __shfl_xor_sync(0xffffffffu, mx1, 1));
        mx1 = fmaxf(mx1, __shfl_xor_sync(0xffffffffu, mx1, 2));
        float mn0 = fmaxf(m0r, mx0), mn1 = fmaxf(m1r, mx1);
        float cr0 = __expf(m0r - mn0), cr1 = __expf(m1r - mn1);
        float sum0 = 0.f, sum1 = 0.f;
#pragma unroll
        for (int nt = 0; nt < 8; nt++) {
            s[nt][0] = __expf(s[nt][0] - mn0);
            s[nt][1] = __expf(s[nt][1] - mn0);
            s[nt][2] = __expf(s[nt][2] - mn1);
            s[nt][3] = __expf(s[nt][3] - mn1);
            sum0 += s[nt][0] + s[nt][1];
            sum1 += s[nt][2] + s[nt][3];
        }
        sum0 += __shfl_xor_sync(0xffffffffu, sum0, 1);
        sum0 += __shfl_xor_sync(0xffffffffu, sum0, 2);
        sum1 += __shfl_xor_sync(0xffffffffu, sum1, 1);
        sum1 += __shfl_xor_sync(0xffffffffu, sum1, 2);
        l0 = l0 * cr0 + sum0;
        l1 = l1 * cr1 + sum1;
        m0r = mn0;
        m1r = mn1;
#pragma unroll
        for (int ne = 0; ne < 8; ne++) {
            of[ne][0] *= cr0; of[ne][1] *= cr0;
            of[ne][2] *= cr1; of[ne][3] *= cr1;
        }

        // ---- P -> warp-private strip (stride 72, proven CF) ----
#pragma unroll
        for (int nt = 0; nt < 8; nt++) {
            int r = lane >> 2;
            int cc = nt * 8 + 2 * (lane & 3);
            Pw[r * 72 + cc]           = f2tf(s[nt][0]);
            Pw[r * 72 + cc + 1]       = f2tf(s[nt][1]);
            Pw[(r + 8) * 72 + cc]     = f2tf(s[nt][2]);
            Pw[(r + 8) * 72 + cc + 1] = f2tf(s[nt][3]);
        }
        __syncwarp();

        // ---- O += P V ----
#pragma unroll
        for (int kb = 0; kb < 8; kb++) {
            uint32_t pa[4];
            pa[0] = Pw[(lane >> 2) * 72 + kb * 8 + (lane & 3)];
            pa[1] = Pw[((lane >> 2) + 8) * 72 + kb * 8 + (lane & 3)];
            pa[2] = Pw[(lane >> 2) * 72 + kb * 8 + (lane & 3) + 4];
            pa[3] = Pw[((lane >> 2) + 8) * 72 + kb * 8 + (lane & 3) + 4];
#pragma unroll
            for (int ne = 0; ne < 8; ne++) {
                uint2 bv = *(const uint2*)&Vs[((kb * 8 + ne) << 6) + lane * 2];
                uint32_t b[2] = {bv.x, bv.y};
                mma8(of[ne], pa, b);
            }
        }
        __syncwarp();
        stage ^= 1;
    }

    // ---- normalize + write ctx (packed A-frag layout, tf32 bits) ----
    float inv0 = 1.f / l0, inv1 = 1.f / l1;
    const int hh = bh % NHEAD;
    const int bb = bh / NHEAD;
    const int qr0 = q0 + w * 16 + (lane >> 2);
    const int qr1 = qr0 + 8;
#pragma unroll
    for (int ne = 0; ne < 8; ne++) {
        int d = hh * 64 + ne * 8 + 2 * (lane & 3);
        int dpart = (d >> 3) * 128 + (d & 3) * 4 + 2 * ((d >> 2) & 1);
        if (qr0 < SEQ_N) {
            int m = bb * SEQ_N + qr0;
            size_t pos = (size_t)(m >> 4) * (KG_D * 128) + dpart
                         + (m & 7) * 16 + ((m >> 3) & 1);
            g_ctxp[pos]     = f2tf(of[ne][0] * inv0);
            g_ctxp[pos + 4] = f2tf(of[ne][1] * inv0);
        }
        if (qr1 < SEQ_N) {
            int m = bb * SEQ_N + qr1;
            size_t pos = (size_t)(m >> 4) * (KG_D * 128) + dpart
                         + (m & 7) * 16 + ((m >> 3) & 1);
            g_ctxp[pos]     = f2tf(of[ne][2] * inv1);
            g_ctxp[pos + 4] = f2tf(of[ne][3] * inv1);
        }
    }
}

// =================================================================
extern "C" void kernel_launch(void* const* d_in, const int* in_sizes, int n_in,
                              void* d_out, int out_size)
{
    const float* x     = (const float*)d_in[0];
    const float* Wqkv  = (const float*)d_in[1];
    const float* Wproj = (const float*)d_in[2];
    const float* bproj = (const float*)d_in[3];
    const float* freqs = (const float*)d_in[4];
    float* out = (float*)d_out;

    uint32_t* xt;  cudaGetSymbolAddress((void**)&xt, g_xt);
    uint32_t* wq;  cudaGetSymbolAddress((void**)&wq, g_wq);
    uint32_t* wp;  cudaGetSymbolAddress((void**)&wp, g_wp);

    cudaFuncSetAttribute(gemm_tc<0>, cudaFuncAttributeMaxDynamicSharedMemorySize,
                         GEMM_SMEM_BYTES);
    cudaFuncSetAttribute(gemm_tc<1>, cudaFuncAttributeMaxDynamicSharedMemorySize,
                         GEMM_SMEM_BYTES);
    cudaFuncSetAttribute(attn_tc, cudaFuncAttributeMaxDynamicSharedMemorySize,
                         ATTN_SMEM_BYTES);

    // 0) prepass: pack inputs + zero K/V pad
    {
        int na = M_ROWS * 192;
        pack_a<<<(na + 255) / 256, 256>>>(x, xt, na);
        int nq = 2304 * 192;
        pack_w<<<(nq + 255) / 256, 256>>>(Wqkv, wq, nq);
        int np = 768 * 192;
        pack_w<<<(np + 255) / 256, 256>>>(Wproj, wp, np);
        zero_pad<<<(NBH * 4096 + 255) / 256, 256>>>();
    }
    // 1) QKV GEMM + fused RoPE -> packed Q/K/V
    {
        dim3 grid((M_ROWS + 127) / 128, (3 * DMODEL) / 128);
        gemm_tc<0><<<grid, 256, GEMM_SMEM_BYTES>>>(nullptr, nullptr, freqs);
    }
    // 2) attention -> packed ctx
    {
        dim3 grid((SEQ_N + 127) / 128, NBH);
        attn_tc<<<grid, 256, ATTN_SMEM_BYTES>>>();
    }
    // 3) proj GEMM + bias -> out
    {
        dim3 grid((M_ROWS + 127) / 128, DMODEL / 128);
        gemm_tc<1><<<grid, 256, GEMM_SMEM_BYTES>>>(out, bproj, nullptr);
    }
}

// round 9
// speedup vs baseline: 3.7405x; 1.7606x over previous
#include <cuda_runtime.h>
#include <cuda_fp16.h>
#include <cstdint>

#define NUM_B 16
#define SEQ_N 1025
#define NHEAD 12
#define HDIM  64
#define DMODEL 768
#define M_ROWS 16400
#define NBH (NUM_B * NHEAD)       // 192

// ---- packed geometry (fp16, k-groups of 16) ----
#define KG 48                     // 768/16
#define A_MG 1025                 // 16400/16
#define APK_SZ (A_MG * KG * 128)  // 6,297,600 u32
#define WQ_NG 288                 // 2304/8
#define WP_NG 96
#define QBUF_BH (65 * 4 * 128)    // 33280 u32 per bh (qg 65 x kg 4 x 128)
#define KVBUF_BH (17 * 2048)      // 34816 u32 per bh (17 tiles x 2048)

// ---------------- scratch (fp16 bit patterns, packed) ----------------
__device__ uint32_t g_xt[APK_SZ];
__device__ uint32_t g_ctxp[APK_SZ];
__device__ uint32_t g_wq[WQ_NG * KG * 64];
__device__ uint32_t g_wp[WP_NG * KG * 64];
__device__ uint32_t g_Q[NBH * QBUF_BH];
__device__ uint32_t g_K[NBH * KVBUF_BH];
__device__ uint32_t g_V[NBH * KVBUF_BH];

__device__ __forceinline__ uint32_t f2h2(float lo, float hi) {
    __half2 h = __floats2half2_rn(lo, hi);
    return *(uint32_t*)&h;
}
__device__ __forceinline__ void mma16(float* c, const uint32_t* a, const uint32_t* b) {
    asm volatile(
        "mma.sync.aligned.m16n8k16.row.col.f32.f16.f16.f32 "
        "{%0,%1,%2,%3}, {%4,%5,%6,%7}, {%8,%9}, {%0,%1,%2,%3};\n"
        : "+f"(c[0]), "+f"(c[1]), "+f"(c[2]), "+f"(c[3])
        : "r"(a[0]), "r"(a[1]), "r"(a[2]), "r"(a[3]), "r"(b[0]), "r"(b[1]));
}
__device__ __forceinline__ void cpa16(uint32_t dst, const void* src, int sz) {
    asm volatile("cp.async.cg.shared.global [%0], [%1], 16, %2;\n"
                 :: "r"(dst), "l"(src), "r"(sz));
}
__device__ __forceinline__ void cpa16u(uint32_t dst, const void* src) {
    asm volatile("cp.async.cg.shared.global [%0], [%1], 16;\n"
                 :: "r"(dst), "l"(src));
}
#define CPA_COMMIT() asm volatile("cp.async.commit_group;\n")
#define CPA_WAIT0()  asm volatile("cp.async.wait_group 0;\n")
#define CPA_WAIT1()  asm volatile("cp.async.wait_group 1;\n")

// ---------------- prepass ----------------
// A-frag layout: [m>>4][k>>4][ ((m&7)*4 + (c&3))*4 + ((m>>3)&1) + 2*((c>>2)&1) ]
// where c = (k>>1)&7 (half2 pair within k-group)
__global__ void pack_a(const float* __restrict__ src, uint32_t* __restrict__ dst, int n)
{
    int id = blockIdx.x * 256 + threadIdx.x;    // (m, pair c 0..383)
    if (id >= n) return;
    int m = id / 384;
    int c = id - m * 384;
    float2 v = *(const float2*)&src[(size_t)m * DMODEL + c * 2];
    dst[((size_t)(m >> 4) * KG + (c >> 3)) * 128
        + ((m & 7) * 4 + (c & 3)) * 4 + ((m >> 3) & 1) + 2 * ((c >> 2) & 1)]
        = f2h2(v.x, v.y);
}
// B-frag layout: [n>>3][k>>4][ ((n&7)*4 + (c&3))*2 + ((c>>2)&1) ]
__global__ void pack_w(const float* __restrict__ src, uint32_t* __restrict__ dst, int n)
{
    int id = blockIdx.x * 256 + threadIdx.x;
    if (id >= n) return;
    int nn = id / 384;
    int c = id - nn * 384;
    float2 v = *(const float2*)&src[(size_t)nn * DMODEL + c * 2];
    dst[((size_t)(nn >> 3) * KG + (c >> 3)) * 64
        + ((nn & 7) * 4 + (c & 3)) * 2 + ((c >> 2) & 1)]
        = f2h2(v.x, v.y);
}
// zero last K/V tile (keys 1024..1087; key 1024 rewritten by gemm0 after)
__global__ void zero_pad()
{
    int id = blockIdx.x * 256 + threadIdx.x;
    if (id >= NBH * 2048) return;
    int bh = id >> 11;
    int i = id & 2047;
    g_K[(size_t)bh * KVBUF_BH + 16 * 2048 + i] = 0;
    g_V[(size_t)bh * KVBUF_BH + 16 * 2048 + i] = 0;
}

// =================================================================
// TN GEMM, fp16 TC (m16n8k16), 3-stage cp.async, packed frags.
// Block 128x128, 256 thr, 8 warps (4m x 2n), warp 32x64, k-step 32.
// Stage: A 2048 u32 | B 2048 u32 = 16KB; 3 stages = 48KB.
// MODE 0: RoPE epilogue -> packed Q/K/V. MODE 1: +bias -> out.
// =================================================================
#define GEMM_SMEM_BYTES (3 * 4096 * 4)

template<int MODE>
__global__ __launch_bounds__(256, 2) void gemm_tc(
    float* __restrict__ out, const float* __restrict__ bias,
    const float* __restrict__ freqs)
{
    extern __shared__ uint32_t gsm[];

    const int tid = threadIdx.x;
    const int lane = tid & 31;
    const int wid = tid >> 5;
    const int wm = wid & 3;
    const int wn = wid >> 2;
    const int m0 = blockIdx.x * 128;
    const int n0 = blockIdx.y * 128;

    const uint32_t* Ag = (MODE == 1) ? g_ctxp : g_xt;
    const uint32_t* Bg = (MODE == 1) ? g_wp : g_wq;

    const uint32_t smAddr = (uint32_t)__cvta_generic_to_shared(gsm);

    float c[2][8][4];
#pragma unroll
    for (int i = 0; i < 2; i++)
#pragma unroll
        for (int j = 0; j < 8; j++)
#pragma unroll
            for (int r = 0; r < 4; r++) c[i][j][r] = 0.f;

    const int s7 = lane >> 2;
    const int l3 = lane & 3;
    const int mg0 = m0 >> 4;
    const int ng0 = n0 >> 3;

    auto stage_ld = [&](int k0, int s) {
        const int kg0 = k0 >> 4;
        // A: 512 chunks (16 blocks x 128 u32)
#pragma unroll
        for (int it = 0; it < 2; it++) {
            int ch = tid + it * 256;
            int blk = ch >> 5;                 // mb = blk>>1, kgi = blk&1
            int inner = (ch & 31) * 4;
            int mg = mg0 + (blk >> 1);
            int sz = (mg < A_MG) ? 16 : 0;
            cpa16(smAddr + (s * 4096 + blk * 128 + inner) * 4,
                  &Ag[((size_t)mg * KG + kg0 + (blk & 1)) * 128 + inner], sz);
        }
        // B: 512 chunks (32 blocks x 64 u32)
#pragma unroll
        for (int it = 0; it < 2; it++) {
            int ch = tid + it * 256;
            int blk = ch >> 4;                 // nb = blk>>1, kgi = blk&1
            int inner = (ch & 15) * 4;
            cpa16u(smAddr + (s * 4096 + 2048 + blk * 64 + inner) * 4,
                   &Bg[((size_t)(ng0 + (blk >> 1)) * KG + kg0 + (blk & 1)) * 64 + inner]);
        }
        CPA_COMMIT();
    };

    stage_ld(0, 0);
    stage_ld(32, 1);

    int stage = 0;
    for (int k0 = 0; k0 < DMODEL; k0 += 32) {
        if (k0 + 32 < DMODEL) CPA_WAIT1(); else CPA_WAIT0();
        __syncthreads();
        if (k0 + 64 < DMODEL) stage_ld(k0 + 64, stage == 0 ? 2 : stage - 1);

        const uint32_t* Ab = gsm + stage * 4096;
        const uint32_t* Bb = Ab + 2048;
#pragma unroll
        for (int kgi = 0; kgi < 2; kgi++) {
            uint32_t a[2][4], b[8][2];
#pragma unroll
            for (int mt = 0; mt < 2; mt++) {
                uint4 av = *(const uint4*)&Ab[(((wm * 2 + mt) * 2 + kgi) << 7) + lane * 4];
                a[mt][0] = av.x; a[mt][1] = av.y; a[mt][2] = av.z; a[mt][3] = av.w;
            }
#pragma unroll
            for (int nt = 0; nt < 8; nt++) {
                uint2 bv = *(const uint2*)&Bb[(((wn * 8 + nt) * 2 + kgi) << 6) + lane * 2];
                b[nt][0] = bv.x; b[nt][1] = bv.y;
            }
#pragma unroll
            for (int mt = 0; mt < 2; mt++)
#pragma unroll
                for (int nt = 0; nt < 8; nt++)
                    mma16(c[mt][nt], a[mt], b[nt]);
        }
        stage = (stage == 2) ? 0 : stage + 1;
    }

    // -------- epilogue --------
    if (MODE == 0) {
        const int sidx = n0 / DMODEL;                 // 0=Q 1=K 2=V
        const int hh = ((n0 % DMODEL) >> 6) + wn;     // head (uniform/warp)
        const float qscale = (sidx == 0) ? 0.125f : 1.0f;
#pragma unroll
        for (int nt = 0; nt < 8; nt++) {
            int e0 = nt * 8 + 2 * l3;
            float f0 = 0.f, f1 = 0.f;
            if (sidx < 2) {
                int fi = hh * 32 + (e0 >> 1);
                f0 = freqs[fi];
                f1 = freqs[384 + fi];
            }
#pragma unroll
            for (int mt = 0; mt < 2; mt++)
#pragma unroll
                for (int hr = 0; hr < 2; hr++) {
                    int row = m0 + wm * 32 + mt * 16 + s7 + hr * 8;
                    if (row >= M_ROWS) continue;
                    int bb = row / SEQ_N;
                    int n = row - bb * SEQ_N;          // token index
                    float v0 = c[mt][nt][hr * 2 + 0];
                    float v1 = c[mt][nt][hr * 2 + 1];
                    if (sidx < 2 && n >= 1) {
                        int t = n - 1;
                        float ang = (float)(t & 31) * f0 + (float)(t >> 5) * f1;
                        float sn, cs;
                        sincosf(ang, &sn, &cs);
                        float a0 = v0, b0 = v1;
                        v0 = a0 * cs - b0 * sn;
                        v1 = a0 * sn + b0 * cs;
                    }
                    int bh = bb * NHEAD + hh;
                    if (sidx == 0) {
                        // Q A-frag: qg = n>>4, kgq = e0>>4
                        size_t pos = (size_t)bh * QBUF_BH
                            + (size_t)((n >> 4) * 4 + (e0 >> 4)) * 128
                            + ((n & 7) * 4 + l3) * 4 + ((n >> 3) & 1) + 2 * (nt & 1);
                        g_Q[pos] = f2h2(v0 * qscale, v1 * qscale);
                    } else if (sidx == 1) {
                        // K B-frag: tile = n>>6, ngL = (n&63)>>3, kgL = e0>>4
                        size_t pos = (size_t)bh * KVBUF_BH + (size_t)(n >> 6) * 2048
                            + (size_t)(((n & 63) >> 3) * 4 + (e0 >> 4)) * 64
                            + ((n & 7) * 4 + l3) * 2 + (nt & 1);
                        g_K[pos] = f2h2(v0, v1);
                    } else {
                        // V B-frag: n-dim = e, k-dim = key(n)
                        int cpair = (n & 15) >> 1;
                        size_t p0 = (size_t)bh * KVBUF_BH + (size_t)(n >> 6) * 2048
                            + (size_t)((e0 >> 3) * 4 + ((n & 63) >> 4)) * 64
                            + (((e0 & 7)) * 4 + (cpair & 3)) * 2 + ((n >> 3) & 1);
                        __half* hp = (__half*)g_V;
                        hp[p0 * 2 + (n & 1)] = __float2half(v0);
                        size_t p1 = p0 + 8;   // e0+1: l' += 4 -> +8 u32... (4*2)
                        hp[p1 * 2 + (n & 1)] = __float2half(v1);
                    }
                }
        }
    } else {
#pragma unroll
        for (int nt = 0; nt < 8; nt++) {
            int col = n0 + wn * 64 + nt * 8 + 2 * l3;
            float b0v = bias[col], b1v = bias[col + 1];
#pragma unroll
            for (int mt = 0; mt < 2; mt++)
#pragma unroll
                for (int hr = 0; hr < 2; hr++) {
                    int row = m0 + wm * 32 + mt * 16 + s7 + hr * 8;
                    if (row >= M_ROWS) continue;
                    *(float2*)&out[(size_t)row * DMODEL + col] =
                        make_float2(c[mt][nt][hr * 2 + 0] + b0v,
                                    c[mt][nt][hr * 2 + 1] + b1v);
                }
        }
    }
}

// =================================================================
// Flash attention, fp16 TC. 256 threads (8 warps), 128 q/block,
// 16 q/warp, kv tiles of 64. Q frags via direct LDG.128 (packed);
// P stays in registers (fp16 C->A frag identity). KV 2-stage cp.async.
// smem: 2 x (K 2048 | V 2048) u32 = 32 KB.
// =================================================================
#define ATTN_SMEM_BYTES (2 * 4096 * 4)

__global__ __launch_bounds__(256, 2) void attn_tc()
{
    extern __shared__ uint32_t dsm[];

    const int tid = threadIdx.x;
    const int lane = tid & 31;
    const int w = tid >> 5;
    const int bx = blockIdx.x;
    const int q0 = bx * 128;
    const int bh = blockIdx.y;

    const uint32_t* Kg = g_K + (size_t)bh * KVBUF_BH;
    const uint32_t* Vg = g_V + (size_t)bh * KVBUF_BH;
    const uint32_t smBase = (uint32_t)__cvta_generic_to_shared(dsm);

    auto issue_kv = [&](int kt, int s) {
        const uint32_t buf = smBase + s * 4096 * 4;
        const uint32_t* ks = Kg + kt * 2048;
        const uint32_t* vs = Vg + kt * 2048;
#pragma unroll
        for (int it = 0; it < 2; it++) {
            int ch = tid + it * 256;
            cpa16u(buf + ch * 16, ks + ch * 4);
            cpa16u(buf + 8192 + ch * 16, vs + ch * 4);
        }
        CPA_COMMIT();
    };

    // ---- Q fragments: direct LDG.128 from packed gmem ----
    const int qg = bx * 8 + w;
    uint32_t qa[4][4];
    if (qg < 65) {
        const uint32_t* Qg = g_Q + (size_t)bh * QBUF_BH + (size_t)qg * 512;
#pragma unroll
        for (int kg = 0; kg < 4; kg++) {
            uint4 qv = *(const uint4*)&Qg[kg * 128 + lane * 4];
            qa[kg][0] = qv.x; qa[kg][1] = qv.y; qa[kg][2] = qv.z; qa[kg][3] = qv.w;
        }
    } else {
#pragma unroll
        for (int kg = 0; kg < 4; kg++)
#pragma unroll
            for (int r = 0; r < 4; r++) qa[kg][r] = 0;
    }

    float of[8][4];
#pragma unroll
    for (int i = 0; i < 8; i++)
#pragma unroll
        for (int j = 0; j < 4; j++) of[i][j] = 0.f;
    float m0r = -1e30f, m1r = -1e30f, l0 = 0.f, l1 = 0.f;

    issue_kv(0, 0);
    int stage = 0;

    for (int kt = 0; kt < 17; kt++) {
        const int kv0 = kt * 64;
        CPA_WAIT0();
        __syncthreads();
        if (kt + 1 < 17) issue_kv(kt + 1, stage ^ 1);

        const uint32_t* Ks = dsm + stage * 4096;
        const uint32_t* Vs = Ks + 2048;

        // ---- S = Q K^T ----
        float s[8][4];
#pragma unroll
        for (int i = 0; i < 8; i++)
#pragma unroll
            for (int j = 0; j < 4; j++) s[i][j] = 0.f;
#pragma unroll
        for (int kg = 0; kg < 4; kg++) {
#pragma unroll
            for (int nt = 0; nt < 8; nt++) {
                uint2 bv = *(const uint2*)&Ks[((nt * 4 + kg) << 6) + lane * 2];
                uint32_t b[2] = {bv.x, bv.y};
                mma16(s[nt], qa[kg], b);
            }
        }

        if (kt == 16) {
#pragma unroll
            for (int nt = 0; nt < 8; nt++) {
                int col = kv0 + nt * 8 + 2 * (lane & 3);
                if (col >= SEQ_N)     { s[nt][0] = -1e30f; s[nt][2] = -1e30f; }
                if (col + 1 >= SEQ_N) { s[nt][1] = -1e30f; s[nt][3] = -1e30f; }
            }
        }

        // ---- online softmax ----
        float mx0 = -1e30f, mx1 = -1e30f;
#pragma unroll
        for (int nt = 0; nt < 8; nt++) {
            mx0 = fmaxf(mx0, fmaxf(s[nt][0], s[nt][1]));
            mx1 = fmaxf(mx1, fmaxf(s[nt][2], s[nt][3]));
        }
        mx0 = fmaxf(mx0, __shfl_xor_sync(0xffffffffu, mx0, 1));
        mx0 = fmaxf(mx0, __shfl_xor_sync(0xffffffffu, mx0, 2));
        mx1 = fmaxf(mx1, __shfl_xor_sync(0xffffffffu, mx1, 1));
        mx1 = fmaxf(mx1, __shfl_xor_sync(0xffffffffu, mx1, 2));
        float mn0 = fmaxf(m0r, mx0), mn1 = fmaxf(m1r, mx1);
        float cr0 = __expf(m0r - mn0), cr1 = __expf(m1r - mn1);
        float sum0 = 0.f, sum1 = 0.f;
#pragma unroll
        for (int nt = 0; nt < 8; nt++) {
            s[nt][0] = __expf(s[nt][0] - mn0);
            s[nt][1] = __expf(s[nt][1] - mn0);
            s[nt][2] = __expf(s[nt][2] - mn1);
            s[nt][3] = __expf(s[nt][3] - mn1);
            sum0 += s[nt][0] + s[nt][1];
            sum1 += s[nt][2] + s[nt][3];
        }
        sum0 += __shfl_xor_sync(0xffffffffu, sum0, 1);
        sum0 += __shfl_xor_sync(0xffffffffu, sum0, 2);
        sum1 += __shfl_xor_sync(0xffffffffu, sum1, 1);
        sum1 += __shfl_xor_sync(0xffffffffu, sum1, 2);
        l0 = l0 * cr0 + sum0;
        l1 = l1 * cr1 + sum1;
        m0r = mn0;
        m1r = mn1;
#pragma unroll
        for (int ne = 0; ne < 8; ne++) {
            of[ne][0] *= cr0; of[ne][1] *= cr0;
            of[ne][2] *= cr1; of[ne][3] *= cr1;
        }

        // ---- O += P V  (P = C-frag == A-frag, register-local) ----
#pragma unroll
        for (int kg = 0; kg < 4; kg++) {
            uint32_t pa[4];
            pa[0] = f2h2(s[2 * kg][0],     s[2 * kg][1]);
            pa[1] = f2h2(s[2 * kg][2],     s[2 * kg][3]);
            pa[2] = f2h2(s[2 * kg + 1][0], s[2 * kg + 1][1]);
            pa[3] = f2h2(s[2 * kg + 1][2], s[2 * kg + 1][3]);
#pragma unroll
            for (int ne = 0; ne < 8; ne++) {
                uint2 bv = *(const uint2*)&Vs[((ne * 4 + kg) << 6) + lane * 2];
                uint32_t b[2] = {bv.x, bv.y};
                mma16(of[ne], pa, b);
            }
        }
        stage ^= 1;
    }

    // ---- normalize + write ctx (packed A-frag, fp16 bits) ----
    float inv0 = 1.f / l0, inv1 = 1.f / l1;
    const int hh = bh % NHEAD;
    const int bb = bh / NHEAD;
    const int l3 = lane & 3;
    const int qr0 = q0 + w * 16 + (lane >> 2);
    const int qr1 = qr0 + 8;
#pragma unroll
    for (int ne = 0; ne < 8; ne++) {
        int d = hh * 64 + ne * 8 + 2 * l3;
        int kg = d >> 4;
        if (qr0 < SEQ_N) {
            int m = bb * SEQ_N + qr0;
            size_t pos = ((size_t)(m >> 4) * KG + kg) * 128
                + ((m & 7) * 4 + l3) * 4 + ((m >> 3) & 1) + 2 * (ne & 1);
            g_ctxp[pos] = f2h2(of[ne][0] * inv0, of[ne][1] * inv0);
        }
        if (qr1 < SEQ_N) {
            int m = bb * SEQ_N + qr1;
            size_t pos = ((size_t)(m >> 4) * KG + kg) * 128
                + ((m & 7) * 4 + l3) * 4 + ((m >> 3) & 1) + 2 * (ne & 1);
            g_ctxp[pos] = f2h2(of[ne][2] * inv1, of[ne][3] * inv1);
        }
    }
}

// =================================================================
extern "C" void kernel_launch(void* const* d_in, const int* in_sizes, int n_in,
                              void* d_out, int out_size)
{
    const float* x     = (const float*)d_in[0];
    const float* Wqkv  = (const float*)d_in[1];
    const float* Wproj = (const float*)d_in[2];
    const float* bproj = (const float*)d_in[3];
    const float* freqs = (const float*)d_in[4];
    float* out = (float*)d_out;

    uint32_t* xt;  cudaGetSymbolAddress((void**)&xt, g_xt);
    uint32_t* wq;  cudaGetSymbolAddress((void**)&wq, g_wq);
    uint32_t* wp;  cudaGetSymbolAddress((void**)&wp, g_wp);

    cudaFuncSetAttribute(gemm_tc<0>, cudaFuncAttributeMaxDynamicSharedMemorySize,
                         GEMM_SMEM_BYTES);
    cudaFuncSetAttribute(gemm_tc<1>, cudaFuncAttributeMaxDynamicSharedMemorySize,
                         GEMM_SMEM_BYTES);
    cudaFuncSetAttribute(attn_tc, cudaFuncAttributeMaxDynamicSharedMemorySize,
                         ATTN_SMEM_BYTES);

    // 0) prepass: pack inputs (fp16) + zero last K/V tile
    {
        int na = M_ROWS * 384;
        pack_a<<<(na + 255) / 256, 256>>>(x, xt, na);
        int nq = 2304 * 384;
        pack_w<<<(nq + 255) / 256, 256>>>(Wqkv, wq, nq);
        int np = 768 * 384;
        pack_w<<<(np + 255) / 256, 256>>>(Wproj, wp, np);
        zero_pad<<<(NBH * 2048 + 255) / 256, 256>>>();
    }
    // 1) QKV GEMM + fused RoPE -> packed Q/K/V
    {
        dim3 grid((M_ROWS + 127) / 128, (3 * DMODEL) / 128);
        gemm_tc<0><<<grid, 256, GEMM_SMEM_BYTES>>>(nullptr, nullptr, freqs);
    }
    // 2) attention -> packed ctx
    {
        dim3 grid((SEQ_N + 127) / 128, NBH);
        attn_tc<<<grid, 256, ATTN_SMEM_BYTES>>>();
    }
    // 3) proj GEMM + bias -> out
    {
        dim3 grid((M_ROWS + 127) / 128, DMODEL / 128);
        gemm_tc<1><<<grid, 256, GEMM_SMEM_BYTES>>>(out, bproj, nullptr);
    }
}